// round 6
// baseline (speedup 1.0000x reference)
#include <cuda_runtime.h>
#include <cstdint>

// ---------------------------------------------------------------------------
// DisenGCN on GB300: fused GEMM(+bias+relu+capsule-normalize) + capsule routing
// N=20000, M=16 neighbors, FEAT=500, d=16, CAPS={8,7,6,5,4,3}, 5 routing iters
// ---------------------------------------------------------------------------

#define NNODES 20000
#define MNBR   16
#define FEAT   500
#define OUTW   656

// scratch (device global; no allocation allowed)
__device__ float g_xnorm[NNODES * 128];  // per-capsule L2-normalized x (compact KD)

// ---------------------------------------------------------------------------
// GEMM: val[M,N] = (relu?)(A[M,K] @ W[N,K]^T + bias[N])
//   epilogue: per-16-col-capsule L2 normalize -> xnorm (compact, row stride N)
//   WRITE_RAW: also store relu'd raw value to rawOut (PCA layer, jump connect)
// BM=128, BN=64, BKK=16, 256 threads, 8x4 per-thread microtile
// ---------------------------------------------------------------------------
#define BM 128
#define BN 64
#define BKK 16

template <bool WRITE_RAW>
__global__ void __launch_bounds__(256) gemm_norm_kernel(
    const float* __restrict__ A, int lda,
    const float* __restrict__ W, int ldw,
    const float* __restrict__ bias,
    float* __restrict__ rawOut, int ldo,
    float* __restrict__ xnorm,
    int Mdim, int Ndim, int Kdim)
{
    __shared__ float As[BKK][BM + 4];
    __shared__ float Ws[BKK][BN + 4];

    const int tid = threadIdx.x;
    const int tx = tid & 15;          // 0..15 -> 4 cols each
    const int ty = tid >> 4;          // 0..15 -> 8 rows each
    const int bm = blockIdx.y * BM;
    const int bn = blockIdx.x * BN;

    float acc[8][4];
#pragma unroll
    for (int i = 0; i < 8; ++i)
#pragma unroll
        for (int j = 0; j < 4; ++j) acc[i][j] = 0.f;

    for (int k0 = 0; k0 < Kdim; k0 += BKK) {
        const bool fullk = (k0 + BKK <= Kdim);
        // ---- load A tile: 512 float4, 2 per thread ----
#pragma unroll
        for (int l = 0; l < 2; ++l) {
            int idx = tid + l * 256;
            int r = idx >> 2;
            int c4 = (idx & 3) * 4;
            int gr = bm + r;
            if (fullk && gr < Mdim) {
                float4 v = *reinterpret_cast<const float4*>(A + (size_t)gr * lda + k0 + c4);
                As[c4 + 0][r] = v.x; As[c4 + 1][r] = v.y;
                As[c4 + 2][r] = v.z; As[c4 + 3][r] = v.w;
            } else {
#pragma unroll
                for (int q = 0; q < 4; ++q) {
                    int gc = k0 + c4 + q;
                    As[c4 + q][r] = (gr < Mdim && gc < Kdim)
                        ? A[(size_t)gr * lda + gc] : 0.f;
                }
            }
        }
        // ---- load W tile: 256 float4, 1 per thread ----
        {
            int r = tid >> 2;
            int c4 = (tid & 3) * 4;
            int gn = bn + r;
            if (fullk && gn < Ndim) {
                float4 v = *reinterpret_cast<const float4*>(W + (size_t)gn * ldw + k0 + c4);
                Ws[c4 + 0][r] = v.x; Ws[c4 + 1][r] = v.y;
                Ws[c4 + 2][r] = v.z; Ws[c4 + 3][r] = v.w;
            } else {
#pragma unroll
                for (int q = 0; q < 4; ++q) {
                    int gc = k0 + c4 + q;
                    Ws[c4 + q][r] = (gn < Ndim && gc < Kdim)
                        ? W[(size_t)gn * ldw + gc] : 0.f;
                }
            }
        }
        __syncthreads();

#pragma unroll
        for (int kk = 0; kk < BKK; ++kk) {
            float a[8], b[4];
#pragma unroll
            for (int i = 0; i < 8; ++i) a[i] = As[kk][ty * 8 + i];
#pragma unroll
            for (int j = 0; j < 4; ++j) b[j] = Ws[kk][tx * 4 + j];
#pragma unroll
            for (int i = 0; i < 8; ++i)
#pragma unroll
                for (int j = 0; j < 4; ++j) acc[i][j] += a[i] * b[j];
        }
        __syncthreads();
    }

    // ---- epilogue: bias (+relu) + per-capsule L2 normalize ----
    const int gc0 = bn + tx * 4;
    float bvals[4];
#pragma unroll
    for (int j = 0; j < 4; ++j) bvals[j] = (gc0 + j < Ndim) ? bias[gc0 + j] : 0.f;

#pragma unroll
    for (int i = 0; i < 8; ++i) {
        int gr = bm + ty * 8 + i;
        float v[4];
        float ssq = 0.f;
#pragma unroll
        for (int j = 0; j < 4; ++j) {
            float val = (gc0 + j < Ndim) ? acc[i][j] + bvals[j] : 0.f;
            if (WRITE_RAW) val = fmaxf(val, 0.f);
            v[j] = val;
            ssq += val * val;
        }
        // capsule (16 cols) spans 4 adjacent lanes (same ty, tx group of 4)
        ssq += __shfl_xor_sync(0xffffffffu, ssq, 1);
        ssq += __shfl_xor_sync(0xffffffffu, ssq, 2);
        float inv = 1.f / fmaxf(sqrtf(ssq), 1e-12f);
        if (gr < Mdim && gc0 < Ndim) {
            if (WRITE_RAW) {
                float4 o = make_float4(v[0], v[1], v[2], v[3]);
                *reinterpret_cast<float4*>(rawOut + (size_t)gr * ldo + gc0) = o;
            }
            float4 no = make_float4(v[0] * inv, v[1] * inv, v[2] * inv, v[3] * inv);
            *reinterpret_cast<float4*>(xnorm + (size_t)gr * Ndim + gc0) = no;
        }
    }
}

// ---------------------------------------------------------------------------
// Routing: one CTA per node, NT = 16*P threads (P = pow2 pad of K).
//  Phase A (scores): tid = m*P + k; z row cached in regs; softmax WITHOUT the
//    max-subtraction (scores are cosines in [-1,1], exp cannot overflow).
//    ps stored K-MAJOR: ps_t[k][m], row stride 20 floats.
//  Phase B (agg): tid = q*2 + g; 8 m's per thread: 4 cached in regs, 4 read
//    from smem per iter (trades LDS for occupancy);
//    ps column read = 2x LDS.128; reduce over g via shfl_xor 1; ssq xor 2,4.
//  __launch_bounds__ caps regs at 64 -> 8 CTAs/SM (occ ~50%).
// ---------------------------------------------------------------------------
template <int K>
__global__ void __launch_bounds__((K > 4) ? 128 : 64, (K > 4) ? 8 : 16)
routing_kernel(
    const float* __restrict__ xnorm,
    const int* __restrict__ nbid,
    float* __restrict__ outp)   // already offset to this layer's column block
{
    constexpr int P  = (K > 4) ? 8 : 4;    // padded capsule count (pow2)
    constexpr int NT = 16 * P;             // threads
    constexpr int KD = K * 16;
    constexpr int Q  = K * 4;              // float4 per node row
    constexpr int UP = 20;                 // u row stride (floats)
    constexpr int PST = 20;                // ps_t row stride (floats): 16 m + pad

    const int n = blockIdx.x;
    const int tid = threadIdx.x;

    __shared__ __align__(16) float z[16 * KD];
    __shared__ __align__(16) float u[8 * UP];
    __shared__ __align__(16) float ps[8 * PST];   // k-major: ps[k*PST + m]

    // init u = normalized self row (padded layout)
    if (tid < Q) {
        float4 v = reinterpret_cast<const float4*>(xnorm + (size_t)n * KD)[tid];
        *reinterpret_cast<float4*>(u + (tid >> 2) * UP + (tid & 3) * 4) = v;
    }

    // gather 16 neighbor rows into z (neighbor ids straight from L1/L2)
    {
        float4* z4 = reinterpret_cast<float4*>(z);
        for (int i = tid; i < 16 * Q; i += NT) {
            int j = i / Q;
            int w = i - j * Q;
            int nbj = __ldg(nbid + n * MNBR + j);
            z4[i] = reinterpret_cast<const float4*>(xnorm + (size_t)nbj * KD)[w];
        }
    }
    __syncthreads();

    // ---- phase-A mapping + reg cache: tid = mA*P + kA ----
    const int mA = tid / P;
    const int kA = tid & (P - 1);
    const bool validA = (kA < K);
    const int kAc = validA ? kA : (K - 1);
    float4 zp[4];
    {
        const float4* src = reinterpret_cast<const float4*>(z + mA * KD + kAc * 16);
        zp[0] = src[0]; zp[1] = src[1]; zp[2] = src[2]; zp[3] = src[3];
    }

    // ---- phase-B mapping: tid = qB*2 + gB (8 m's per thread) ----
    const int qB = tid >> 1;
    const int gB = tid & 1;
    const bool validB = (tid < 2 * Q);
    const int qc = validB ? qB : (Q - 1);
    const int kB = qc >> 2;                // capsule of this q
    // half the m-rows cached in regs (m = 8gB .. 8gB+3); other half from smem
    float4 za[4];
#pragma unroll
    for (int j = 0; j < 4; ++j)
        za[j] = reinterpret_cast<const float4*>(z)[(8 * gB + j) * Q + qc];
    const float4* zlo = reinterpret_cast<const float4*>(z) + (8 * gB + 4) * Q + qc;
    // self slice for aggregation (added once, after g-reduction)
    float4 xs4 = *reinterpret_cast<const float4*>(u + kB * UP + (qc & 3) * 4);

#pragma unroll
    for (int t = 0; t < 5; ++t) {
        // ---- A: agreement p[m][k] = <z[m,k,:], u[k,:]> ----
        float p;
        {
            const float4* up = reinterpret_cast<const float4*>(u + kAc * UP);
            float pv = 0.f;
#pragma unroll
            for (int q = 0; q < 4; ++q) {
                float4 uu = up[q];
                pv += zp[q].x * uu.x + zp[q].y * uu.y + zp[q].z * uu.z + zp[q].w * uu.w;
            }
            p = validA ? pv : -1e30f;
        }
        // softmax over capsules (no max-sub: |p|<=1, padding exp -> 0)
        float e = __expf(p);
        float s = e;
        s += __shfl_xor_sync(0xffffffffu, s, 1);
        s += __shfl_xor_sync(0xffffffffu, s, 2);
        if (P == 8) s += __shfl_xor_sync(0xffffffffu, s, 4);
        float pr = __fdividef(e, s);
        if (validA) ps[kA * PST + mA] = pr;     // k-major scatter (conflict-free)
        __syncthreads();

        // ---- B: u[k][:] = xself + sum_m z[m][k][:] * p[m][k] ----
        float4 pa = *reinterpret_cast<const float4*>(ps + kB * PST + 8 * gB);
        float4 pb = *reinterpret_cast<const float4*>(ps + kB * PST + 8 * gB + 4);
        float4 acc = make_float4(0.f, 0.f, 0.f, 0.f);
        {
            float pmr[4] = {pa.x, pa.y, pa.z, pa.w};
#pragma unroll
            for (int j = 0; j < 4; ++j) {
                acc.x += za[j].x * pmr[j]; acc.y += za[j].y * pmr[j];
                acc.z += za[j].z * pmr[j]; acc.w += za[j].w * pmr[j];
            }
            float pms[4] = {pb.x, pb.y, pb.z, pb.w};
#pragma unroll
            for (int j = 0; j < 4; ++j) {
                float4 zm = zlo[j * Q];
                acc.x += zm.x * pms[j]; acc.y += zm.y * pms[j];
                acc.z += zm.z * pms[j]; acc.w += zm.w * pms[j];
            }
        }
        // reduce over the 2 m-groups (adjacent lanes)
        acc.x += __shfl_xor_sync(0xffffffffu, acc.x, 1);
        acc.y += __shfl_xor_sync(0xffffffffu, acc.y, 1);
        acc.z += __shfl_xor_sync(0xffffffffu, acc.z, 1);
        acc.w += __shfl_xor_sync(0xffffffffu, acc.w, 1);
        acc.x += xs4.x; acc.y += xs4.y; acc.z += xs4.z; acc.w += xs4.w;

        if (t < 4) {
            // capsule L2: capsule spans 8 adjacent lanes (4 chunks x 2 dup)
            float sq = acc.x * acc.x + acc.y * acc.y + acc.z * acc.z + acc.w * acc.w;
            sq += __shfl_xor_sync(0xffffffffu, sq, 2);
            sq += __shfl_xor_sync(0xffffffffu, sq, 4);
            float inv = rsqrtf(fmaxf(sq, 1e-24f));
            if (validB && gB == 0) {
                float4 o = make_float4(acc.x * inv, acc.y * inv, acc.z * inv, acc.w * inv);
                *reinterpret_cast<float4*>(u + kB * UP + (qB & 3) * 4) = o;
            }
            __syncthreads();
        } else if (validB && gB == 0) {
            float4 o = make_float4(fmaxf(acc.x, 0.f), fmaxf(acc.y, 0.f),
                                   fmaxf(acc.z, 0.f), fmaxf(acc.w, 0.f));
            *reinterpret_cast<float4*>(outp + (size_t)n * OUTW + qB * 4) = o;
        }
    }
}

// ---------------------------------------------------------------------------
// host orchestration
// ---------------------------------------------------------------------------
extern "C" void kernel_launch(void* const* d_in, const int* in_sizes, int n_in,
                              void* d_out, int out_size)
{
    (void)in_sizes; (void)n_in; (void)out_size;
    const float* feature = (const float*)d_in[0];
    const int*   nbid    = (const int*)d_in[1];
    const float* pca_w   = (const float*)d_in[2];
    const float* pca_b   = (const float*)d_in[3];
    const float* W[6]  = {nullptr, (const float*)d_in[4], (const float*)d_in[6],
                          (const float*)d_in[8], (const float*)d_in[10], (const float*)d_in[12]};
    const float* Bb[6] = {nullptr, (const float*)d_in[5], (const float*)d_in[7],
                          (const float*)d_in[9], (const float*)d_in[11], (const float*)d_in[13]};
    float* out = (float*)d_out;

    static const int caps[6]   = {8, 7, 6, 5, 4, 3};
    static const int coloff[7] = {0, 128, 256, 368, 464, 544, 608};

    float* xnorm;
    cudaGetSymbolAddress((void**)&xnorm, g_xnorm);

    const int mblocks = (NNODES + BM - 1) / BM;   // 157

    // PCA: x0 = relu(feature @ pca_w.T + pca_b) -> out[:,0:128] + xnorm
    {
        dim3 grid((128 + BN - 1) / BN, mblocks);
        gemm_norm_kernel<true><<<grid, 256>>>(feature, FEAT, pca_w, FEAT, pca_b,
                                              out, OUTW, xnorm, NNODES, 128, FEAT);
    }

    for (int i = 0; i < 6; ++i) {
        int k = caps[i];
        int kd = k * 16;
        if (i > 0) {
            int fin = caps[i - 1] * 16;
            dim3 grid((kd + BN - 1) / BN, mblocks);
            gemm_norm_kernel<false><<<grid, 256>>>(out + coloff[i], OUTW,
                                                   W[i], fin, Bb[i],
                                                   nullptr, 0, xnorm,
                                                   NNODES, kd, fin);
        }
        float* dst = out + coloff[i + 1];
        switch (k) {
            case 8: routing_kernel<8><<<NNODES, 128>>>(xnorm, nbid, dst); break;
            case 7: routing_kernel<7><<<NNODES, 128>>>(xnorm, nbid, dst); break;
            case 6: routing_kernel<6><<<NNODES, 128>>>(xnorm, nbid, dst); break;
            case 5: routing_kernel<5><<<NNODES, 128>>>(xnorm, nbid, dst); break;
            case 4: routing_kernel<4><<<NNODES, 64>>>(xnorm, nbid, dst); break;
            case 3: routing_kernel<3><<<NNODES, 64>>>(xnorm, nbid, dst); break;
        }
    }
}

// round 7
// speedup vs baseline: 1.0980x; 1.0980x over previous
#include <cuda_runtime.h>
#include <cstdint>

// ---------------------------------------------------------------------------
// DisenGCN on GB300: fused GEMM(+bias+relu+capsule-normalize) + capsule routing
// N=20000, M=16 neighbors, FEAT=500, d=16, CAPS={8,7,6,5,4,3}, 5 routing iters
// ---------------------------------------------------------------------------

#define NNODES 20000
#define MNBR   16
#define FEAT   500
#define OUTW   656

// scratch (device global; no allocation allowed)
__device__ float g_xnorm[NNODES * 128];  // per-capsule L2-normalized x (compact KD)

// ---------------------------------------------------------------------------
// GEMM: val[M,N] = (relu?)(A[M,K] @ W[N,K]^T + bias[N])
//   epilogue: per-16-col-capsule L2 normalize -> xnorm (compact, row stride N)
//   WRITE_RAW: also store relu'd raw value to rawOut (PCA layer, jump connect)
// BM=128, BN=64, BKK=16, 256 threads, 8x4 microtile,
// double-buffered smem + register prefetch (1 barrier per k-tile).
// ---------------------------------------------------------------------------
#define BM 128
#define BN 64
#define BKK 16

__device__ __forceinline__ float4 ldg4_guard(
    const float* __restrict__ P, int gr, int Rdim, int gc, int Kdim, int ld)
{
    float4 v = make_float4(0.f, 0.f, 0.f, 0.f);
    if (gr < Rdim) {
        if (gc + 3 < Kdim) {
            v = *reinterpret_cast<const float4*>(P + (size_t)gr * ld + gc);
        } else {
            const float* row = P + (size_t)gr * ld;
            if (gc + 0 < Kdim) v.x = row[gc + 0];
            if (gc + 1 < Kdim) v.y = row[gc + 1];
            if (gc + 2 < Kdim) v.z = row[gc + 2];
            if (gc + 3 < Kdim) v.w = row[gc + 3];
        }
    }
    return v;
}

template <bool WRITE_RAW>
__global__ void __launch_bounds__(256) gemm_norm_kernel(
    const float* __restrict__ A, int lda,
    const float* __restrict__ W, int ldw,
    const float* __restrict__ bias,
    float* __restrict__ rawOut, int ldo,
    float* __restrict__ xnorm,
    int Mdim, int Ndim, int Kdim)
{
    __shared__ float As[2][BKK][BM + 4];
    __shared__ float Ws[2][BKK][BN + 4];

    const int tid = threadIdx.x;
    const int tx = tid & 15;          // 0..15 -> 4 cols each
    const int ty = tid >> 4;          // 0..15 -> 8 rows each
    const int bm = blockIdx.y * BM;
    const int bn = blockIdx.x * BN;

    // loader lanes
    const int ar0 = tid >> 2;               // A rows: ar0 and ar0+64... (2 loads)
    const int ac4 = (tid & 3) * 4;
    const int ar1 = (tid + 256) >> 2;
    const int wr  = tid >> 2;               // W row

    float acc[8][4];
#pragma unroll
    for (int i = 0; i < 8; ++i)
#pragma unroll
        for (int j = 0; j < 4; ++j) acc[i][j] = 0.f;

    const int nk = (Kdim + BKK - 1) / BKK;

    float4 av0, av1, wv0;
    // prefetch tile 0
    av0 = ldg4_guard(A, bm + ar0, Mdim, 0 + ac4, Kdim, lda);
    av1 = ldg4_guard(A, bm + ar1, Mdim, 0 + ac4, Kdim, lda);
    wv0 = ldg4_guard(W, bn + wr,  Ndim, 0 + ac4, Kdim, ldw);
    // store tile 0 -> buffer 0
    {
        As[0][ac4 + 0][ar0] = av0.x; As[0][ac4 + 1][ar0] = av0.y;
        As[0][ac4 + 2][ar0] = av0.z; As[0][ac4 + 3][ar0] = av0.w;
        As[0][ac4 + 0][ar1] = av1.x; As[0][ac4 + 1][ar1] = av1.y;
        As[0][ac4 + 2][ar1] = av1.z; As[0][ac4 + 3][ar1] = av1.w;
        Ws[0][ac4 + 0][wr]  = wv0.x; Ws[0][ac4 + 1][wr]  = wv0.y;
        Ws[0][ac4 + 2][wr]  = wv0.z; Ws[0][ac4 + 3][wr]  = wv0.w;
    }
    __syncthreads();

    for (int it = 0; it < nk; ++it) {
        const int buf = it & 1;
        // prefetch next tile into registers (latency hidden behind FMAs)
        if (it + 1 < nk) {
            int k0 = (it + 1) * BKK;
            av0 = ldg4_guard(A, bm + ar0, Mdim, k0 + ac4, Kdim, lda);
            av1 = ldg4_guard(A, bm + ar1, Mdim, k0 + ac4, Kdim, lda);
            wv0 = ldg4_guard(W, bn + wr,  Ndim, k0 + ac4, Kdim, ldw);
        }

#pragma unroll
        for (int kk = 0; kk < BKK; ++kk) {
            float a[8], b[4];
#pragma unroll
            for (int i = 0; i < 8; ++i) a[i] = As[buf][kk][ty * 8 + i];
#pragma unroll
            for (int j = 0; j < 4; ++j) b[j] = Ws[buf][kk][tx * 4 + j];
#pragma unroll
            for (int i = 0; i < 8; ++i)
#pragma unroll
                for (int j = 0; j < 4; ++j) acc[i][j] += a[i] * b[j];
        }

        if (it + 1 < nk) {
            const int nbuf = buf ^ 1;
            // safe: barrier at end of previous iter guarantees nobody still
            // reads nbuf; current readers use buf.
            As[nbuf][ac4 + 0][ar0] = av0.x; As[nbuf][ac4 + 1][ar0] = av0.y;
            As[nbuf][ac4 + 2][ar0] = av0.z; As[nbuf][ac4 + 3][ar0] = av0.w;
            As[nbuf][ac4 + 0][ar1] = av1.x; As[nbuf][ac4 + 1][ar1] = av1.y;
            As[nbuf][ac4 + 2][ar1] = av1.z; As[nbuf][ac4 + 3][ar1] = av1.w;
            Ws[nbuf][ac4 + 0][wr]  = wv0.x; Ws[nbuf][ac4 + 1][wr]  = wv0.y;
            Ws[nbuf][ac4 + 2][wr]  = wv0.z; Ws[nbuf][ac4 + 3][wr]  = wv0.w;
            __syncthreads();
        }
    }

    // ---- epilogue: bias (+relu) + per-capsule L2 normalize ----
    const int gc0 = bn + tx * 4;
    float bvals[4];
#pragma unroll
    for (int j = 0; j < 4; ++j) bvals[j] = (gc0 + j < Ndim) ? bias[gc0 + j] : 0.f;

#pragma unroll
    for (int i = 0; i < 8; ++i) {
        int gr = bm + ty * 8 + i;
        float v[4];
        float ssq = 0.f;
#pragma unroll
        for (int j = 0; j < 4; ++j) {
            float val = (gc0 + j < Ndim) ? acc[i][j] + bvals[j] : 0.f;
            if (WRITE_RAW) val = fmaxf(val, 0.f);
            v[j] = val;
            ssq += val * val;
        }
        // capsule (16 cols) spans 4 adjacent lanes (same ty, tx group of 4)
        ssq += __shfl_xor_sync(0xffffffffu, ssq, 1);
        ssq += __shfl_xor_sync(0xffffffffu, ssq, 2);
        float inv = 1.f / fmaxf(sqrtf(ssq), 1e-12f);
        if (gr < Mdim && gc0 < Ndim) {
            if (WRITE_RAW) {
                float4 o = make_float4(v[0], v[1], v[2], v[3]);
                *reinterpret_cast<float4*>(rawOut + (size_t)gr * ldo + gc0) = o;
            }
            float4 no = make_float4(v[0] * inv, v[1] * inv, v[2] * inv, v[3] * inv);
            *reinterpret_cast<float4*>(xnorm + (size_t)gr * Ndim + gc0) = no;
        }
    }
}

// ---------------------------------------------------------------------------
// Routing (R5 winner, reverted): one CTA per node, NT = 16*P threads.
//  Phase A: tid = m*P + k; z row in regs; softmax without max-sub;
//           ps stored K-MAJOR (stride 20), conflict-free scatter.
//  Phase B: tid = q*2 + g; 8 m's per thread fully cached in regs (za[8]);
//           ps column read = 2x LDS.128; g-reduce shfl_xor 1; ssq xor 2,4.
// ---------------------------------------------------------------------------
template <int K>
__global__ void __launch_bounds__((K > 4) ? 128 : 64) routing_kernel(
    const float* __restrict__ xnorm,
    const int* __restrict__ nbid,
    float* __restrict__ outp)   // already offset to this layer's column block
{
    constexpr int P  = (K > 4) ? 8 : 4;    // padded capsule count (pow2)
    constexpr int NT = 16 * P;             // threads
    constexpr int KD = K * 16;
    constexpr int Q  = K * 4;              // float4 per node row
    constexpr int UP = 20;                 // u row stride (floats)
    constexpr int PST = 20;                // ps_t row stride (floats): 16 m + pad

    const int n = blockIdx.x;
    const int tid = threadIdx.x;

    __shared__ __align__(16) float z[16 * KD];
    __shared__ __align__(16) float u[8 * UP];
    __shared__ __align__(16) float ps[8 * PST];   // k-major: ps[k*PST + m]

    // init u = normalized self row (padded layout)
    if (tid < Q) {
        float4 v = reinterpret_cast<const float4*>(xnorm + (size_t)n * KD)[tid];
        *reinterpret_cast<float4*>(u + (tid >> 2) * UP + (tid & 3) * 4) = v;
    }

    // gather 16 neighbor rows into z (neighbor ids straight from L1/L2)
    {
        float4* z4 = reinterpret_cast<float4*>(z);
        for (int i = tid; i < 16 * Q; i += NT) {
            int j = i / Q;
            int w = i - j * Q;
            int nbj = __ldg(nbid + n * MNBR + j);
            z4[i] = reinterpret_cast<const float4*>(xnorm + (size_t)nbj * KD)[w];
        }
    }
    __syncthreads();

    // ---- phase-A mapping + reg cache: tid = mA*P + kA ----
    const int mA = tid / P;
    const int kA = tid & (P - 1);
    const bool validA = (kA < K);
    const int kAc = validA ? kA : (K - 1);
    float4 zp[4];
    {
        const float4* src = reinterpret_cast<const float4*>(z + mA * KD + kAc * 16);
        zp[0] = src[0]; zp[1] = src[1]; zp[2] = src[2]; zp[3] = src[3];
    }

    // ---- phase-B mapping + reg cache: tid = qB*2 + gB (8 m's per thread) ----
    const int qB = tid >> 1;
    const int gB = tid & 1;
    const bool validB = (tid < 2 * Q);
    const int qc = validB ? qB : (Q - 1);
    const int kB = qc >> 2;                // capsule of this q
    float4 za[8];
#pragma unroll
    for (int j = 0; j < 8; ++j)
        za[j] = reinterpret_cast<const float4*>(z)[(8 * gB + j) * Q + qc];
    // self slice for aggregation (added once, after g-reduction)
    float4 xs4 = *reinterpret_cast<const float4*>(u + kB * UP + (qc & 3) * 4);

#pragma unroll
    for (int t = 0; t < 5; ++t) {
        // ---- A: agreement p[m][k] = <z[m,k,:], u[k,:]> ----
        float p;
        {
            const float4* up = reinterpret_cast<const float4*>(u + kAc * UP);
            float pv = 0.f;
#pragma unroll
            for (int q = 0; q < 4; ++q) {
                float4 uu = up[q];
                pv += zp[q].x * uu.x + zp[q].y * uu.y + zp[q].z * uu.z + zp[q].w * uu.w;
            }
            p = validA ? pv : -1e30f;
        }
        // softmax over capsules (no max-sub: |p|<=1, padding exp -> 0)
        float e = __expf(p);
        float s = e;
        s += __shfl_xor_sync(0xffffffffu, s, 1);
        s += __shfl_xor_sync(0xffffffffu, s, 2);
        if (P == 8) s += __shfl_xor_sync(0xffffffffu, s, 4);
        float pr = __fdividef(e, s);
        if (validA) ps[kA * PST + mA] = pr;     // k-major scatter (conflict-free)
        __syncthreads();

        // ---- B: u[k][:] = xself + sum_m z[m][k][:] * p[m][k] ----
        float4 pa = *reinterpret_cast<const float4*>(ps + kB * PST + 8 * gB);
        float4 pb = *reinterpret_cast<const float4*>(ps + kB * PST + 8 * gB + 4);
        float pm[8] = {pa.x, pa.y, pa.z, pa.w, pb.x, pb.y, pb.z, pb.w};
        float4 acc = make_float4(0.f, 0.f, 0.f, 0.f);
#pragma unroll
        for (int j = 0; j < 8; ++j) {
            acc.x += za[j].x * pm[j]; acc.y += za[j].y * pm[j];
            acc.z += za[j].z * pm[j]; acc.w += za[j].w * pm[j];
        }
        // reduce over the 2 m-groups (adjacent lanes)
        acc.x += __shfl_xor_sync(0xffffffffu, acc.x, 1);
        acc.y += __shfl_xor_sync(0xffffffffu, acc.y, 1);
        acc.z += __shfl_xor_sync(0xffffffffu, acc.z, 1);
        acc.w += __shfl_xor_sync(0xffffffffu, acc.w, 1);
        acc.x += xs4.x; acc.y += xs4.y; acc.z += xs4.z; acc.w += xs4.w;

        if (t < 4) {
            // capsule L2: capsule spans 8 adjacent lanes (4 chunks x 2 dup)
            float sq = acc.x * acc.x + acc.y * acc.y + acc.z * acc.z + acc.w * acc.w;
            sq += __shfl_xor_sync(0xffffffffu, sq, 2);
            sq += __shfl_xor_sync(0xffffffffu, sq, 4);
            float inv = rsqrtf(fmaxf(sq, 1e-24f));
            if (validB && gB == 0) {
                float4 o = make_float4(acc.x * inv, acc.y * inv, acc.z * inv, acc.w * inv);
                *reinterpret_cast<float4*>(u + kB * UP + (qB & 3) * 4) = o;
            }
            __syncthreads();
        } else if (validB && gB == 0) {
            float4 o = make_float4(fmaxf(acc.x, 0.f), fmaxf(acc.y, 0.f),
                                   fmaxf(acc.z, 0.f), fmaxf(acc.w, 0.f));
            *reinterpret_cast<float4*>(outp + (size_t)n * OUTW + qB * 4) = o;
        }
    }
}

// ---------------------------------------------------------------------------
// host orchestration
// ---------------------------------------------------------------------------
extern "C" void kernel_launch(void* const* d_in, const int* in_sizes, int n_in,
                              void* d_out, int out_size)
{
    (void)in_sizes; (void)n_in; (void)out_size;
    const float* feature = (const float*)d_in[0];
    const int*   nbid    = (const int*)d_in[1];
    const float* pca_w   = (const float*)d_in[2];
    const float* pca_b   = (const float*)d_in[3];
    const float* W[6]  = {nullptr, (const float*)d_in[4], (const float*)d_in[6],
                          (const float*)d_in[8], (const float*)d_in[10], (const float*)d_in[12]};
    const float* Bb[6] = {nullptr, (const float*)d_in[5], (const float*)d_in[7],
                          (const float*)d_in[9], (const float*)d_in[11], (const float*)d_in[13]};
    float* out = (float*)d_out;

    static const int caps[6]   = {8, 7, 6, 5, 4, 3};
    static const int coloff[7] = {0, 128, 256, 368, 464, 544, 608};

    float* xnorm;
    cudaGetSymbolAddress((void**)&xnorm, g_xnorm);

    const int mblocks = (NNODES + BM - 1) / BM;   // 157

    // PCA: x0 = relu(feature @ pca_w.T + pca_b) -> out[:,0:128] + xnorm
    {
        dim3 grid((128 + BN - 1) / BN, mblocks);
        gemm_norm_kernel<true><<<grid, 256>>>(feature, FEAT, pca_w, FEAT, pca_b,
                                              out, OUTW, xnorm, NNODES, 128, FEAT);
    }

    for (int i = 0; i < 6; ++i) {
        int k = caps[i];
        int kd = k * 16;
        if (i > 0) {
            int fin = caps[i - 1] * 16;
            dim3 grid((kd + BN - 1) / BN, mblocks);
            gemm_norm_kernel<false><<<grid, 256>>>(out + coloff[i], OUTW,
                                                   W[i], fin, Bb[i],
                                                   nullptr, 0, xnorm,
                                                   NNODES, kd, fin);
        }
        float* dst = out + coloff[i + 1];
        switch (k) {
            case 8: routing_kernel<8><<<NNODES, 128>>>(xnorm, nbid, dst); break;
            case 7: routing_kernel<7><<<NNODES, 128>>>(xnorm, nbid, dst); break;
            case 6: routing_kernel<6><<<NNODES, 128>>>(xnorm, nbid, dst); break;
            case 5: routing_kernel<5><<<NNODES, 128>>>(xnorm, nbid, dst); break;
            case 4: routing_kernel<4><<<NNODES, 64>>>(xnorm, nbid, dst); break;
            case 3: routing_kernel<3><<<NNODES, 64>>>(xnorm, nbid, dst); break;
        }
    }
}

// round 8
// speedup vs baseline: 1.3206x; 1.2028x over previous
#include <cuda_runtime.h>
#include <cuda_fp16.h>
#include <cstdint>

// ---------------------------------------------------------------------------
// DisenGCN on GB300: fused GEMM(+bias+relu+capsule-normalize) + capsule routing
// N=20000, M=16 neighbors, FEAT=500, d=16, CAPS={8,7,6,5,4,3}, 5 routing iters
// Routing gathers neighbor capsules from an fp16 mirror of xnorm (halves the
// random-L2 sector count that dominates T_CTA); all arithmetic stays fp32.
// ---------------------------------------------------------------------------

#define NNODES 20000
#define MNBR   16
#define FEAT   500
#define OUTW   656

// scratch (device globals; no allocation allowed)
__device__ float  g_xnorm [NNODES * 128];  // fp32 normalized x (self row, exactness)
__device__ __half g_xnormh[NNODES * 128];  // fp16 mirror (neighbor gather)

// ---------------------------------------------------------------------------
// GEMM: val[M,N] = (relu?)(A[M,K] @ W[N,K]^T + bias[N])
//   epilogue: per-16-col-capsule L2 normalize -> xnorm (fp32) + xnormh (fp16)
//   WRITE_RAW: also store relu'd raw value to rawOut (PCA layer, jump connect)
// BM=128, BN=64, BKK=16, 256 threads, 8x4 microtile, double-buffered smem.
// ---------------------------------------------------------------------------
#define BM 128
#define BN 64
#define BKK 16

__device__ __forceinline__ float4 ldg4_guard(
    const float* __restrict__ P, int gr, int Rdim, int gc, int Kdim, int ld)
{
    float4 v = make_float4(0.f, 0.f, 0.f, 0.f);
    if (gr < Rdim) {
        if (gc + 3 < Kdim) {
            v = *reinterpret_cast<const float4*>(P + (size_t)gr * ld + gc);
        } else {
            const float* row = P + (size_t)gr * ld;
            if (gc + 0 < Kdim) v.x = row[gc + 0];
            if (gc + 1 < Kdim) v.y = row[gc + 1];
            if (gc + 2 < Kdim) v.z = row[gc + 2];
            if (gc + 3 < Kdim) v.w = row[gc + 3];
        }
    }
    return v;
}

template <bool WRITE_RAW>
__global__ void __launch_bounds__(256) gemm_norm_kernel(
    const float* __restrict__ A, int lda,
    const float* __restrict__ W, int ldw,
    const float* __restrict__ bias,
    float* __restrict__ rawOut, int ldo,
    float* __restrict__ xnorm,
    __half* __restrict__ xnormh,
    int Mdim, int Ndim, int Kdim)
{
    __shared__ float As[2][BKK][BM + 4];
    __shared__ float Ws[2][BKK][BN + 4];

    const int tid = threadIdx.x;
    const int tx = tid & 15;          // 0..15 -> 4 cols each
    const int ty = tid >> 4;          // 0..15 -> 8 rows each
    const int bm = blockIdx.y * BM;
    const int bn = blockIdx.x * BN;

    const int ar0 = tid >> 2;
    const int ac4 = (tid & 3) * 4;
    const int ar1 = (tid + 256) >> 2;
    const int wr  = tid >> 2;

    float acc[8][4];
#pragma unroll
    for (int i = 0; i < 8; ++i)
#pragma unroll
        for (int j = 0; j < 4; ++j) acc[i][j] = 0.f;

    const int nk = (Kdim + BKK - 1) / BKK;

    float4 av0, av1, wv0;
    av0 = ldg4_guard(A, bm + ar0, Mdim, 0 + ac4, Kdim, lda);
    av1 = ldg4_guard(A, bm + ar1, Mdim, 0 + ac4, Kdim, lda);
    wv0 = ldg4_guard(W, bn + wr,  Ndim, 0 + ac4, Kdim, ldw);
    {
        As[0][ac4 + 0][ar0] = av0.x; As[0][ac4 + 1][ar0] = av0.y;
        As[0][ac4 + 2][ar0] = av0.z; As[0][ac4 + 3][ar0] = av0.w;
        As[0][ac4 + 0][ar1] = av1.x; As[0][ac4 + 1][ar1] = av1.y;
        As[0][ac4 + 2][ar1] = av1.z; As[0][ac4 + 3][ar1] = av1.w;
        Ws[0][ac4 + 0][wr]  = wv0.x; Ws[0][ac4 + 1][wr]  = wv0.y;
        Ws[0][ac4 + 2][wr]  = wv0.z; Ws[0][ac4 + 3][wr]  = wv0.w;
    }
    __syncthreads();

    for (int it = 0; it < nk; ++it) {
        const int buf = it & 1;
        if (it + 1 < nk) {
            int k0 = (it + 1) * BKK;
            av0 = ldg4_guard(A, bm + ar0, Mdim, k0 + ac4, Kdim, lda);
            av1 = ldg4_guard(A, bm + ar1, Mdim, k0 + ac4, Kdim, lda);
            wv0 = ldg4_guard(W, bn + wr,  Ndim, k0 + ac4, Kdim, ldw);
        }

#pragma unroll
        for (int kk = 0; kk < BKK; ++kk) {
            float a[8], b[4];
#pragma unroll
            for (int i = 0; i < 8; ++i) a[i] = As[buf][kk][ty * 8 + i];
#pragma unroll
            for (int j = 0; j < 4; ++j) b[j] = Ws[buf][kk][tx * 4 + j];
#pragma unroll
            for (int i = 0; i < 8; ++i)
#pragma unroll
                for (int j = 0; j < 4; ++j) acc[i][j] += a[i] * b[j];
        }

        if (it + 1 < nk) {
            const int nbuf = buf ^ 1;
            As[nbuf][ac4 + 0][ar0] = av0.x; As[nbuf][ac4 + 1][ar0] = av0.y;
            As[nbuf][ac4 + 2][ar0] = av0.z; As[nbuf][ac4 + 3][ar0] = av0.w;
            As[nbuf][ac4 + 0][ar1] = av1.x; As[nbuf][ac4 + 1][ar1] = av1.y;
            As[nbuf][ac4 + 2][ar1] = av1.z; As[nbuf][ac4 + 3][ar1] = av1.w;
            Ws[nbuf][ac4 + 0][wr]  = wv0.x; Ws[nbuf][ac4 + 1][wr]  = wv0.y;
            Ws[nbuf][ac4 + 2][wr]  = wv0.z; Ws[nbuf][ac4 + 3][wr]  = wv0.w;
            __syncthreads();
        }
    }

    // ---- epilogue: bias (+relu) + per-capsule L2 normalize ----
    const int gc0 = bn + tx * 4;
    float bvals[4];
#pragma unroll
    for (int j = 0; j < 4; ++j) bvals[j] = (gc0 + j < Ndim) ? bias[gc0 + j] : 0.f;

#pragma unroll
    for (int i = 0; i < 8; ++i) {
        int gr = bm + ty * 8 + i;
        float v[4];
        float ssq = 0.f;
#pragma unroll
        for (int j = 0; j < 4; ++j) {
            float val = (gc0 + j < Ndim) ? acc[i][j] + bvals[j] : 0.f;
            if (WRITE_RAW) val = fmaxf(val, 0.f);
            v[j] = val;
            ssq += val * val;
        }
        ssq += __shfl_xor_sync(0xffffffffu, ssq, 1);
        ssq += __shfl_xor_sync(0xffffffffu, ssq, 2);
        float inv = 1.f / fmaxf(sqrtf(ssq), 1e-12f);
        if (gr < Mdim && gc0 < Ndim) {
            if (WRITE_RAW) {
                float4 o = make_float4(v[0], v[1], v[2], v[3]);
                *reinterpret_cast<float4*>(rawOut + (size_t)gr * ldo + gc0) = o;
            }
            float4 no = make_float4(v[0] * inv, v[1] * inv, v[2] * inv, v[3] * inv);
            *reinterpret_cast<float4*>(xnorm + (size_t)gr * Ndim + gc0) = no;
            __half2 h0 = __floats2half2_rn(no.x, no.y);
            __half2 h1 = __floats2half2_rn(no.z, no.w);
            uint2 hp;
            hp.x = *reinterpret_cast<uint32_t*>(&h0);
            hp.y = *reinterpret_cast<uint32_t*>(&h1);
            *reinterpret_cast<uint2*>(xnormh + (size_t)gr * Ndim + gc0) = hp;
        }
    }
}

// ---------------------------------------------------------------------------
// Routing: one CTA per node, NT = 16*P threads. Gather z from fp16 mirror
// (half the sectors); convert ONCE into fp32 register caches; iteration loop
// identical to the R5/R7 winner (k-major ps, no-max softmax).
// ---------------------------------------------------------------------------
__device__ __forceinline__ float4 h4_to_f4(uint32_t lo, uint32_t hi)
{
    __half2 a = *reinterpret_cast<__half2*>(&lo);
    __half2 b = *reinterpret_cast<__half2*>(&hi);
    float2 fa = __half22float2(a);
    float2 fb = __half22float2(b);
    return make_float4(fa.x, fa.y, fb.x, fb.y);
}

template <int K>
__global__ void __launch_bounds__((K > 4) ? 128 : 64) routing_kernel(
    const float*  __restrict__ xnorm,
    const __half* __restrict__ xnormh,
    const int*    __restrict__ nbid,
    float* __restrict__ outp)   // already offset to this layer's column block
{
    constexpr int P  = (K > 4) ? 8 : 4;    // padded capsule count (pow2)
    constexpr int NT = 16 * P;             // threads
    constexpr int KD = K * 16;
    constexpr int Q  = K * 4;              // float4 per node row
    constexpr int RH = KD / 8;             // uint4 (8 halves) per row
    constexpr int UP = 20;                 // u row stride (floats)
    constexpr int PST = 20;                // ps_t row stride (floats)

    const int n = blockIdx.x;
    const int tid = threadIdx.x;

    __shared__ __align__(16) __half zh[16 * KD];  // fp16 z tile
    __shared__ __align__(16) float u[8 * UP];
    __shared__ __align__(16) float ps[8 * PST];   // k-major: ps[k*PST + m]

    // init u = normalized self row (fp32, padded layout)
    if (tid < Q) {
        float4 v = reinterpret_cast<const float4*>(xnorm + (size_t)n * KD)[tid];
        *reinterpret_cast<float4*>(u + (tid >> 2) * UP + (tid & 3) * 4) = v;
    }

    // gather 16 neighbor rows (fp16) into zh: 16*RH uint4 total
    {
        uint4* zd = reinterpret_cast<uint4*>(zh);
        for (int i = tid; i < 16 * RH; i += NT) {
            int j = i / RH;
            int w = i - j * RH;
            int nbj = __ldg(nbid + n * MNBR + j);
            zd[i] = reinterpret_cast<const uint4*>(xnormh + (size_t)nbj * KD)[w];
        }
    }
    __syncthreads();

    // ---- phase-A mapping + fp32 reg cache: tid = mA*P + kA ----
    const int mA = tid / P;
    const int kA = tid & (P - 1);
    const bool validA = (kA < K);
    const int kAc = validA ? kA : (K - 1);
    float4 zp[4];
    {
        const uint4* src = reinterpret_cast<const uint4*>(zh + mA * KD + kAc * 16);
        uint4 r0 = src[0], r1 = src[1];
        zp[0] = h4_to_f4(r0.x, r0.y);
        zp[1] = h4_to_f4(r0.z, r0.w);
        zp[2] = h4_to_f4(r1.x, r1.y);
        zp[3] = h4_to_f4(r1.z, r1.w);
    }

    // ---- phase-B mapping + fp32 reg cache: tid = qB*2 + gB (8 m's/thread) ----
    const int qB = tid >> 1;
    const int gB = tid & 1;
    const bool validB = (tid < 2 * Q);
    const int qc = validB ? qB : (Q - 1);
    const int kB = qc >> 2;                // capsule of this q
    float4 za[8];
#pragma unroll
    for (int j = 0; j < 8; ++j) {
        uint2 rv = *reinterpret_cast<const uint2*>(zh + (8 * gB + j) * KD + qc * 4);
        za[j] = h4_to_f4(rv.x, rv.y);
    }
    // self slice for aggregation (fp32)
    float4 xs4 = *reinterpret_cast<const float4*>(u + kB * UP + (qc & 3) * 4);

#pragma unroll
    for (int t = 0; t < 5; ++t) {
        // ---- A: agreement p[m][k] = <z[m,k,:], u[k,:]> ----
        float p;
        {
            const float4* up = reinterpret_cast<const float4*>(u + kAc * UP);
            float pv = 0.f;
#pragma unroll
            for (int q = 0; q < 4; ++q) {
                float4 uu = up[q];
                pv += zp[q].x * uu.x + zp[q].y * uu.y + zp[q].z * uu.z + zp[q].w * uu.w;
            }
            p = validA ? pv : -1e30f;
        }
        // softmax over capsules (no max-sub: |p|<=1, padding exp -> 0)
        float e = __expf(p);
        float s = e;
        s += __shfl_xor_sync(0xffffffffu, s, 1);
        s += __shfl_xor_sync(0xffffffffu, s, 2);
        if (P == 8) s += __shfl_xor_sync(0xffffffffu, s, 4);
        float pr = __fdividef(e, s);
        if (validA) ps[kA * PST + mA] = pr;     // k-major scatter (conflict-free)
        __syncthreads();

        // ---- B: u[k][:] = xself + sum_m z[m][k][:] * p[m][k] ----
        float4 pa = *reinterpret_cast<const float4*>(ps + kB * PST + 8 * gB);
        float4 pb = *reinterpret_cast<const float4*>(ps + kB * PST + 8 * gB + 4);
        float pm[8] = {pa.x, pa.y, pa.z, pa.w, pb.x, pb.y, pb.z, pb.w};
        float4 acc = make_float4(0.f, 0.f, 0.f, 0.f);
#pragma unroll
        for (int j = 0; j < 8; ++j) {
            acc.x += za[j].x * pm[j]; acc.y += za[j].y * pm[j];
            acc.z += za[j].z * pm[j]; acc.w += za[j].w * pm[j];
        }
        acc.x += __shfl_xor_sync(0xffffffffu, acc.x, 1);
        acc.y += __shfl_xor_sync(0xffffffffu, acc.y, 1);
        acc.z += __shfl_xor_sync(0xffffffffu, acc.z, 1);
        acc.w += __shfl_xor_sync(0xffffffffu, acc.w, 1);
        acc.x += xs4.x; acc.y += xs4.y; acc.z += xs4.z; acc.w += xs4.w;

        if (t < 4) {
            float sq = acc.x * acc.x + acc.y * acc.y + acc.z * acc.z + acc.w * acc.w;
            sq += __shfl_xor_sync(0xffffffffu, sq, 2);
            sq += __shfl_xor_sync(0xffffffffu, sq, 4);
            float inv = rsqrtf(fmaxf(sq, 1e-24f));
            if (validB && gB == 0) {
                float4 o = make_float4(acc.x * inv, acc.y * inv, acc.z * inv, acc.w * inv);
                *reinterpret_cast<float4*>(u + kB * UP + (qB & 3) * 4) = o;
            }
            __syncthreads();
        } else if (validB && gB == 0) {
            float4 o = make_float4(fmaxf(acc.x, 0.f), fmaxf(acc.y, 0.f),
                                   fmaxf(acc.z, 0.f), fmaxf(acc.w, 0.f));
            *reinterpret_cast<float4*>(outp + (size_t)n * OUTW + qB * 4) = o;
        }
    }
}

// ---------------------------------------------------------------------------
// host orchestration
// ---------------------------------------------------------------------------
extern "C" void kernel_launch(void* const* d_in, const int* in_sizes, int n_in,
                              void* d_out, int out_size)
{
    (void)in_sizes; (void)n_in; (void)out_size;
    const float* feature = (const float*)d_in[0];
    const int*   nbid    = (const int*)d_in[1];
    const float* pca_w   = (const float*)d_in[2];
    const float* pca_b   = (const float*)d_in[3];
    const float* W[6]  = {nullptr, (const float*)d_in[4], (const float*)d_in[6],
                          (const float*)d_in[8], (const float*)d_in[10], (const float*)d_in[12]};
    const float* Bb[6] = {nullptr, (const float*)d_in[5], (const float*)d_in[7],
                          (const float*)d_in[9], (const float*)d_in[11], (const float*)d_in[13]};
    float* out = (float*)d_out;

    static const int caps[6]   = {8, 7, 6, 5, 4, 3};
    static const int coloff[7] = {0, 128, 256, 368, 464, 544, 608};

    float* xnorm;
    __half* xnormh;
    cudaGetSymbolAddress((void**)&xnorm,  g_xnorm);
    cudaGetSymbolAddress((void**)&xnormh, g_xnormh);

    const int mblocks = (NNODES + BM - 1) / BM;   // 157

    // PCA: x0 = relu(feature @ pca_w.T + pca_b) -> out[:,0:128] + xnorm(+h)
    {
        dim3 grid((128 + BN - 1) / BN, mblocks);
        gemm_norm_kernel<true><<<grid, 256>>>(feature, FEAT, pca_w, FEAT, pca_b,
                                              out, OUTW, xnorm, xnormh,
                                              NNODES, 128, FEAT);
    }

    for (int i = 0; i < 6; ++i) {
        int k = caps[i];
        int kd = k * 16;
        if (i > 0) {
            int fin = caps[i - 1] * 16;
            dim3 grid((kd + BN - 1) / BN, mblocks);
            gemm_norm_kernel<false><<<grid, 256>>>(out + coloff[i], OUTW,
                                                   W[i], fin, Bb[i],
                                                   nullptr, 0, xnorm, xnormh,
                                                   NNODES, kd, fin);
        }
        float* dst = out + coloff[i + 1];
        switch (k) {
            case 8: routing_kernel<8><<<NNODES, 128>>>(xnorm, xnormh, nbid, dst); break;
            case 7: routing_kernel<7><<<NNODES, 128>>>(xnorm, xnormh, nbid, dst); break;
            case 6: routing_kernel<6><<<NNODES, 128>>>(xnorm, xnormh, nbid, dst); break;
            case 5: routing_kernel<5><<<NNODES, 128>>>(xnorm, xnormh, nbid, dst); break;
            case 4: routing_kernel<4><<<NNODES, 64>>>(xnorm, xnormh, nbid, dst); break;
            case 3: routing_kernel<3><<<NNODES, 64>>>(xnorm, xnormh, nbid, dst); break;
        }
    }
}

// round 9
// speedup vs baseline: 1.3678x; 1.0357x over previous
#include <cuda_runtime.h>
#include <cuda_fp16.h>
#include <cstdint>

// ---------------------------------------------------------------------------
// DisenGCN on GB300: fused GEMM(+bias+relu+capsule-normalize) + capsule routing
// N=20000, M=16 neighbors, FEAT=500, d=16, CAPS={8,7,6,5,4,3}, 5 routing iters
// Routing: z gathered straight into registers from an fp16 mirror of xnorm
// (no smem staging); compute fp32; k-major ps; no-max softmax.
// ---------------------------------------------------------------------------

#define NNODES 20000
#define MNBR   16
#define FEAT   500
#define OUTW   656

// scratch (device globals; no allocation allowed)
__device__ float  g_xnorm [NNODES * 128];  // fp32 normalized x (self row, exactness)
__device__ __half g_xnormh[NNODES * 128];  // fp16 mirror (neighbor gather)

// ---------------------------------------------------------------------------
// GEMM: val[M,N] = (relu?)(A[M,K] @ W[N,K]^T + bias[N])
//   epilogue: per-16-col-capsule L2 normalize -> xnorm (fp32) + xnormh (fp16)
//   WRITE_RAW: also store relu'd raw value to rawOut (PCA layer, jump connect)
// BM=128, BN=64, BKK=16, 256 threads, 8x4 microtile, double-buffered smem.
// ---------------------------------------------------------------------------
#define BM 128
#define BN 64
#define BKK 16

__device__ __forceinline__ float4 ldg4_guard(
    const float* __restrict__ P, int gr, int Rdim, int gc, int Kdim, int ld)
{
    float4 v = make_float4(0.f, 0.f, 0.f, 0.f);
    if (gr < Rdim) {
        if (gc + 3 < Kdim) {
            v = *reinterpret_cast<const float4*>(P + (size_t)gr * ld + gc);
        } else {
            const float* row = P + (size_t)gr * ld;
            if (gc + 0 < Kdim) v.x = row[gc + 0];
            if (gc + 1 < Kdim) v.y = row[gc + 1];
            if (gc + 2 < Kdim) v.z = row[gc + 2];
            if (gc + 3 < Kdim) v.w = row[gc + 3];
        }
    }
    return v;
}

template <bool WRITE_RAW>
__global__ void __launch_bounds__(256) gemm_norm_kernel(
    const float* __restrict__ A, int lda,
    const float* __restrict__ W, int ldw,
    const float* __restrict__ bias,
    float* __restrict__ rawOut, int ldo,
    float* __restrict__ xnorm,
    __half* __restrict__ xnormh,
    int Mdim, int Ndim, int Kdim)
{
    __shared__ float As[2][BKK][BM + 4];
    __shared__ float Ws[2][BKK][BN + 4];

    const int tid = threadIdx.x;
    const int tx = tid & 15;          // 0..15 -> 4 cols each
    const int ty = tid >> 4;          // 0..15 -> 8 rows each
    const int bm = blockIdx.y * BM;
    const int bn = blockIdx.x * BN;

    const int ar0 = tid >> 2;
    const int ac4 = (tid & 3) * 4;
    const int ar1 = (tid + 256) >> 2;
    const int wr  = tid >> 2;

    float acc[8][4];
#pragma unroll
    for (int i = 0; i < 8; ++i)
#pragma unroll
        for (int j = 0; j < 4; ++j) acc[i][j] = 0.f;

    const int nk = (Kdim + BKK - 1) / BKK;

    float4 av0, av1, wv0;
    av0 = ldg4_guard(A, bm + ar0, Mdim, 0 + ac4, Kdim, lda);
    av1 = ldg4_guard(A, bm + ar1, Mdim, 0 + ac4, Kdim, lda);
    wv0 = ldg4_guard(W, bn + wr,  Ndim, 0 + ac4, Kdim, ldw);
    {
        As[0][ac4 + 0][ar0] = av0.x; As[0][ac4 + 1][ar0] = av0.y;
        As[0][ac4 + 2][ar0] = av0.z; As[0][ac4 + 3][ar0] = av0.w;
        As[0][ac4 + 0][ar1] = av1.x; As[0][ac4 + 1][ar1] = av1.y;
        As[0][ac4 + 2][ar1] = av1.z; As[0][ac4 + 3][ar1] = av1.w;
        Ws[0][ac4 + 0][wr]  = wv0.x; Ws[0][ac4 + 1][wr]  = wv0.y;
        Ws[0][ac4 + 2][wr]  = wv0.z; Ws[0][ac4 + 3][wr]  = wv0.w;
    }
    __syncthreads();

    for (int it = 0; it < nk; ++it) {
        const int buf = it & 1;
        if (it + 1 < nk) {
            int k0 = (it + 1) * BKK;
            av0 = ldg4_guard(A, bm + ar0, Mdim, k0 + ac4, Kdim, lda);
            av1 = ldg4_guard(A, bm + ar1, Mdim, k0 + ac4, Kdim, lda);
            wv0 = ldg4_guard(W, bn + wr,  Ndim, k0 + ac4, Kdim, ldw);
        }

#pragma unroll
        for (int kk = 0; kk < BKK; ++kk) {
            float a[8], b[4];
#pragma unroll
            for (int i = 0; i < 8; ++i) a[i] = As[buf][kk][ty * 8 + i];
#pragma unroll
            for (int j = 0; j < 4; ++j) b[j] = Ws[buf][kk][tx * 4 + j];
#pragma unroll
            for (int i = 0; i < 8; ++i)
#pragma unroll
                for (int j = 0; j < 4; ++j) acc[i][j] += a[i] * b[j];
        }

        if (it + 1 < nk) {
            const int nbuf = buf ^ 1;
            As[nbuf][ac4 + 0][ar0] = av0.x; As[nbuf][ac4 + 1][ar0] = av0.y;
            As[nbuf][ac4 + 2][ar0] = av0.z; As[nbuf][ac4 + 3][ar0] = av0.w;
            As[nbuf][ac4 + 0][ar1] = av1.x; As[nbuf][ac4 + 1][ar1] = av1.y;
            As[nbuf][ac4 + 2][ar1] = av1.z; As[nbuf][ac4 + 3][ar1] = av1.w;
            Ws[nbuf][ac4 + 0][wr]  = wv0.x; Ws[nbuf][ac4 + 1][wr]  = wv0.y;
            Ws[nbuf][ac4 + 2][wr]  = wv0.z; Ws[nbuf][ac4 + 3][wr]  = wv0.w;
            __syncthreads();
        }
    }

    // ---- epilogue: bias (+relu) + per-capsule L2 normalize ----
    const int gc0 = bn + tx * 4;
    float bvals[4];
#pragma unroll
    for (int j = 0; j < 4; ++j) bvals[j] = (gc0 + j < Ndim) ? bias[gc0 + j] : 0.f;

#pragma unroll
    for (int i = 0; i < 8; ++i) {
        int gr = bm + ty * 8 + i;
        float v[4];
        float ssq = 0.f;
#pragma unroll
        for (int j = 0; j < 4; ++j) {
            float val = (gc0 + j < Ndim) ? acc[i][j] + bvals[j] : 0.f;
            if (WRITE_RAW) val = fmaxf(val, 0.f);
            v[j] = val;
            ssq += val * val;
        }
        ssq += __shfl_xor_sync(0xffffffffu, ssq, 1);
        ssq += __shfl_xor_sync(0xffffffffu, ssq, 2);
        float inv = 1.f / fmaxf(sqrtf(ssq), 1e-12f);
        if (gr < Mdim && gc0 < Ndim) {
            if (WRITE_RAW) {
                float4 o = make_float4(v[0], v[1], v[2], v[3]);
                *reinterpret_cast<float4*>(rawOut + (size_t)gr * ldo + gc0) = o;
            }
            float4 no = make_float4(v[0] * inv, v[1] * inv, v[2] * inv, v[3] * inv);
            *reinterpret_cast<float4*>(xnorm + (size_t)gr * Ndim + gc0) = no;
            __half2 h0 = __floats2half2_rn(no.x, no.y);
            __half2 h1 = __floats2half2_rn(no.z, no.w);
            uint2 hp;
            hp.x = *reinterpret_cast<uint32_t*>(&h0);
            hp.y = *reinterpret_cast<uint32_t*>(&h1);
            *reinterpret_cast<uint2*>(xnormh + (size_t)gr * Ndim + gc0) = hp;
        }
    }
}

// ---------------------------------------------------------------------------
// Routing: one CTA per node, NT = 16*P threads. No smem z tile:
//  phase-A slice (z[mA][kA][:]) loaded by 2 direct LDG.128 -> fp32 regs;
//  phase-B slices (8 m-rows x 4 elems) loaded by 8 LDG.64 -> fp16 regs
//  (converted per use). Iteration loop: k-major ps, no-max softmax,
//  2 barriers/iter.
// ---------------------------------------------------------------------------
__device__ __forceinline__ float4 h4_to_f4(uint32_t lo, uint32_t hi)
{
    __half2 a = *reinterpret_cast<__half2*>(&lo);
    __half2 b = *reinterpret_cast<__half2*>(&hi);
    float2 fa = __half22float2(a);
    float2 fb = __half22float2(b);
    return make_float4(fa.x, fa.y, fb.x, fb.y);
}

template <int K>
__global__ void __launch_bounds__((K > 4) ? 128 : 64, (K > 4) ? 8 : 16)
routing_kernel(
    const float*  __restrict__ xnorm,
    const __half* __restrict__ xnormh,
    const int*    __restrict__ nbid,
    float* __restrict__ outp)   // already offset to this layer's column block
{
    constexpr int P  = (K > 4) ? 8 : 4;    // padded capsule count (pow2)
    constexpr int KD = K * 16;
    constexpr int Q  = K * 4;              // float4 per node row
    constexpr int UP = 20;                 // u row stride (floats)
    constexpr int PST = 20;                // ps_t row stride (floats)

    const int n = blockIdx.x;
    const int tid = threadIdx.x;

    __shared__ __align__(16) float u[8 * UP];
    __shared__ __align__(16) float ps[8 * PST];   // k-major: ps[k*PST + m]
    __shared__ int nb[16];

    if (tid < 16) nb[tid] = __ldg(nbid + n * MNBR + tid);

    // init u = normalized self row (fp32, padded layout)
    if (tid < Q) {
        float4 v = reinterpret_cast<const float4*>(xnorm + (size_t)n * KD)[tid];
        *reinterpret_cast<float4*>(u + (tid >> 2) * UP + (tid & 3) * 4) = v;
    }
    __syncthreads();

    // ---- phase-A mapping + fp32 reg slice (direct LDG from fp16 mirror) ----
    const int mA = tid / P;
    const int kA = tid & (P - 1);
    const bool validA = (kA < K);
    const int kAc = validA ? kA : (K - 1);
    float4 zp[4];
    {
        const uint4* rowA = reinterpret_cast<const uint4*>(
            xnormh + (size_t)nb[mA] * KD + kAc * 16);
        uint4 r0 = __ldg(rowA);
        uint4 r1 = __ldg(rowA + 1);
        zp[0] = h4_to_f4(r0.x, r0.y);
        zp[1] = h4_to_f4(r0.z, r0.w);
        zp[2] = h4_to_f4(r1.x, r1.y);
        zp[3] = h4_to_f4(r1.z, r1.w);
    }

    // ---- phase-B mapping + fp16 reg slices: tid = qB*2 + gB (8 m's/thread) ----
    const int qB = tid >> 1;
    const int gB = tid & 1;
    const bool validB = (tid < 2 * Q);
    const int qc = validB ? qB : (Q - 1);
    const int kB = qc >> 2;                // capsule of this q
    uint2 zah[8];
#pragma unroll
    for (int j = 0; j < 8; ++j)
        zah[j] = __ldg(reinterpret_cast<const uint2*>(
            xnormh + (size_t)nb[8 * gB + j] * KD + qc * 4));
    // self slice for aggregation (fp32, from u smem post-barrier)
    float4 xs4 = *reinterpret_cast<const float4*>(u + kB * UP + (qc & 3) * 4);

#pragma unroll
    for (int t = 0; t < 5; ++t) {
        // ---- A: agreement p[m][k] = <z[m,k,:], u[k,:]> ----
        float p;
        {
            const float4* up = reinterpret_cast<const float4*>(u + kAc * UP);
            float pv = 0.f;
#pragma unroll
            for (int q = 0; q < 4; ++q) {
                float4 uu = up[q];
                pv += zp[q].x * uu.x + zp[q].y * uu.y + zp[q].z * uu.z + zp[q].w * uu.w;
            }
            p = validA ? pv : -1e30f;
        }
        // softmax over capsules (no max-sub: |p|<=1, padding exp -> 0)
        float e = __expf(p);
        float s = e;
        s += __shfl_xor_sync(0xffffffffu, s, 1);
        s += __shfl_xor_sync(0xffffffffu, s, 2);
        if (P == 8) s += __shfl_xor_sync(0xffffffffu, s, 4);
        float pr = __fdividef(e, s);
        if (validA) ps[kA * PST + mA] = pr;     // k-major scatter (conflict-free)
        __syncthreads();

        // ---- B: u[k][:] = xself + sum_m z[m][k][:] * p[m][k] ----
        float4 pa = *reinterpret_cast<const float4*>(ps + kB * PST + 8 * gB);
        float4 pb = *reinterpret_cast<const float4*>(ps + kB * PST + 8 * gB + 4);
        float pm[8] = {pa.x, pa.y, pa.z, pa.w, pb.x, pb.y, pb.z, pb.w};
        float4 acc = make_float4(0.f, 0.f, 0.f, 0.f);
#pragma unroll
        for (int j = 0; j < 8; ++j) {
            float4 zm = h4_to_f4(zah[j].x, zah[j].y);
            acc.x += zm.x * pm[j]; acc.y += zm.y * pm[j];
            acc.z += zm.z * pm[j]; acc.w += zm.w * pm[j];
        }
        acc.x += __shfl_xor_sync(0xffffffffu, acc.x, 1);
        acc.y += __shfl_xor_sync(0xffffffffu, acc.y, 1);
        acc.z += __shfl_xor_sync(0xffffffffu, acc.z, 1);
        acc.w += __shfl_xor_sync(0xffffffffu, acc.w, 1);
        acc.x += xs4.x; acc.y += xs4.y; acc.z += xs4.z; acc.w += xs4.w;

        if (t < 4) {
            float sq = acc.x * acc.x + acc.y * acc.y + acc.z * acc.z + acc.w * acc.w;
            sq += __shfl_xor_sync(0xffffffffu, sq, 2);
            sq += __shfl_xor_sync(0xffffffffu, sq, 4);
            float inv = rsqrtf(fmaxf(sq, 1e-24f));
            if (validB && gB == 0) {
                float4 o = make_float4(acc.x * inv, acc.y * inv, acc.z * inv, acc.w * inv);
                *reinterpret_cast<float4*>(u + kB * UP + (qB & 3) * 4) = o;
            }
            __syncthreads();
        } else if (validB && gB == 0) {
            float4 o = make_float4(fmaxf(acc.x, 0.f), fmaxf(acc.y, 0.f),
                                   fmaxf(acc.z, 0.f), fmaxf(acc.w, 0.f));
            *reinterpret_cast<float4*>(outp + (size_t)n * OUTW + qB * 4) = o;
        }
    }
}

// ---------------------------------------------------------------------------
// host orchestration
// ---------------------------------------------------------------------------
extern "C" void kernel_launch(void* const* d_in, const int* in_sizes, int n_in,
                              void* d_out, int out_size)
{
    (void)in_sizes; (void)n_in; (void)out_size;
    const float* feature = (const float*)d_in[0];
    const int*   nbid    = (const int*)d_in[1];
    const float* pca_w   = (const float*)d_in[2];
    const float* pca_b   = (const float*)d_in[3];
    const float* W[6]  = {nullptr, (const float*)d_in[4], (const float*)d_in[6],
                          (const float*)d_in[8], (const float*)d_in[10], (const float*)d_in[12]};
    const float* Bb[6] = {nullptr, (const float*)d_in[5], (const float*)d_in[7],
                          (const float*)d_in[9], (const float*)d_in[11], (const float*)d_in[13]};
    float* out = (float*)d_out;

    static const int caps[6]   = {8, 7, 6, 5, 4, 3};
    static const int coloff[7] = {0, 128, 256, 368, 464, 544, 608};

    float* xnorm;
    __half* xnormh;
    cudaGetSymbolAddress((void**)&xnorm,  g_xnorm);
    cudaGetSymbolAddress((void**)&xnormh, g_xnormh);

    const int mblocks = (NNODES + BM - 1) / BM;   // 157

    // PCA: x0 = relu(feature @ pca_w.T + pca_b) -> out[:,0:128] + xnorm(+h)
    {
        dim3 grid((128 + BN - 1) / BN, mblocks);
        gemm_norm_kernel<true><<<grid, 256>>>(feature, FEAT, pca_w, FEAT, pca_b,
                                              out, OUTW, xnorm, xnormh,
                                              NNODES, 128, FEAT);
    }

    for (int i = 0; i < 6; ++i) {
        int k = caps[i];
        int kd = k * 16;
        if (i > 0) {
            int fin = caps[i - 1] * 16;
            dim3 grid((kd + BN - 1) / BN, mblocks);
            gemm_norm_kernel<false><<<grid, 256>>>(out + coloff[i], OUTW,
                                                   W[i], fin, Bb[i],
                                                   nullptr, 0, xnorm, xnormh,
                                                   NNODES, kd, fin);
        }
        float* dst = out + coloff[i + 1];
        switch (k) {
            case 8: routing_kernel<8><<<NNODES, 128>>>(xnorm, xnormh, nbid, dst); break;
            case 7: routing_kernel<7><<<NNODES, 128>>>(xnorm, xnormh, nbid, dst); break;
            case 6: routing_kernel<6><<<NNODES, 128>>>(xnorm, xnormh, nbid, dst); break;
            case 5: routing_kernel<5><<<NNODES, 128>>>(xnorm, xnormh, nbid, dst); break;
            case 4: routing_kernel<4><<<NNODES, 64>>>(xnorm, xnormh, nbid, dst); break;
            case 3: routing_kernel<3><<<NNODES, 64>>>(xnorm, xnormh, nbid, dst); break;
        }
    }
}

// round 10
// speedup vs baseline: 1.4584x; 1.0663x over previous
#include <cuda_runtime.h>
#include <cuda_fp16.h>
#include <cstdint>

// ---------------------------------------------------------------------------
// DisenGCN on GB300: fused GEMM(+bias+relu+capsule-normalize) + capsule routing
// N=20000, M=16 neighbors, FEAT=500, d=16, CAPS={8,7,6,5,4,3}, 5 routing iters
// Routing: z direct-LDG from fp16 mirror; u kept fp16 in smem; compute fp32.
// ---------------------------------------------------------------------------

#define NNODES 20000
#define MNBR   16
#define FEAT   500
#define OUTW   656

// scratch (device globals; no allocation allowed)
__device__ float  g_xnorm [NNODES * 128];  // fp32 normalized x (self row, exactness)
__device__ __half g_xnormh[NNODES * 128];  // fp16 mirror (neighbor gather)

// ---------------------------------------------------------------------------
// GEMM: val[M,N] = (relu?)(A[M,K] @ W[N,K]^T + bias[N])
//   epilogue: per-16-col-capsule L2 normalize -> xnorm (fp32) + xnormh (fp16)
// BM=128, BN=64, BKK=16, 256 threads, 8x4 microtile, double-buffered smem.
// ---------------------------------------------------------------------------
#define BM 128
#define BN 64
#define BKK 16

__device__ __forceinline__ float4 ldg4_guard(
    const float* __restrict__ P, int gr, int Rdim, int gc, int Kdim, int ld)
{
    float4 v = make_float4(0.f, 0.f, 0.f, 0.f);
    if (gr < Rdim) {
        if (gc + 3 < Kdim) {
            v = *reinterpret_cast<const float4*>(P + (size_t)gr * ld + gc);
        } else {
            const float* row = P + (size_t)gr * ld;
            if (gc + 0 < Kdim) v.x = row[gc + 0];
            if (gc + 1 < Kdim) v.y = row[gc + 1];
            if (gc + 2 < Kdim) v.z = row[gc + 2];
            if (gc + 3 < Kdim) v.w = row[gc + 3];
        }
    }
    return v;
}

template <bool WRITE_RAW>
__global__ void __launch_bounds__(256) gemm_norm_kernel(
    const float* __restrict__ A, int lda,
    const float* __restrict__ W, int ldw,
    const float* __restrict__ bias,
    float* __restrict__ rawOut, int ldo,
    float* __restrict__ xnorm,
    __half* __restrict__ xnormh,
    int Mdim, int Ndim, int Kdim)
{
    __shared__ float As[2][BKK][BM + 4];
    __shared__ float Ws[2][BKK][BN + 4];

    const int tid = threadIdx.x;
    const int tx = tid & 15;
    const int ty = tid >> 4;
    const int bm = blockIdx.y * BM;
    const int bn = blockIdx.x * BN;

    const int ar0 = tid >> 2;
    const int ac4 = (tid & 3) * 4;
    const int ar1 = (tid + 256) >> 2;
    const int wr  = tid >> 2;

    float acc[8][4];
#pragma unroll
    for (int i = 0; i < 8; ++i)
#pragma unroll
        for (int j = 0; j < 4; ++j) acc[i][j] = 0.f;

    const int nk = (Kdim + BKK - 1) / BKK;

    float4 av0, av1, wv0;
    av0 = ldg4_guard(A, bm + ar0, Mdim, 0 + ac4, Kdim, lda);
    av1 = ldg4_guard(A, bm + ar1, Mdim, 0 + ac4, Kdim, lda);
    wv0 = ldg4_guard(W, bn + wr,  Ndim, 0 + ac4, Kdim, ldw);
    {
        As[0][ac4 + 0][ar0] = av0.x; As[0][ac4 + 1][ar0] = av0.y;
        As[0][ac4 + 2][ar0] = av0.z; As[0][ac4 + 3][ar0] = av0.w;
        As[0][ac4 + 0][ar1] = av1.x; As[0][ac4 + 1][ar1] = av1.y;
        As[0][ac4 + 2][ar1] = av1.z; As[0][ac4 + 3][ar1] = av1.w;
        Ws[0][ac4 + 0][wr]  = wv0.x; Ws[0][ac4 + 1][wr]  = wv0.y;
        Ws[0][ac4 + 2][wr]  = wv0.z; Ws[0][ac4 + 3][wr]  = wv0.w;
    }
    __syncthreads();

    for (int it = 0; it < nk; ++it) {
        const int buf = it & 1;
        if (it + 1 < nk) {
            int k0 = (it + 1) * BKK;
            av0 = ldg4_guard(A, bm + ar0, Mdim, k0 + ac4, Kdim, lda);
            av1 = ldg4_guard(A, bm + ar1, Mdim, k0 + ac4, Kdim, lda);
            wv0 = ldg4_guard(W, bn + wr,  Ndim, k0 + ac4, Kdim, ldw);
        }

#pragma unroll
        for (int kk = 0; kk < BKK; ++kk) {
            float a[8], b[4];
#pragma unroll
            for (int i = 0; i < 8; ++i) a[i] = As[buf][kk][ty * 8 + i];
#pragma unroll
            for (int j = 0; j < 4; ++j) b[j] = Ws[buf][kk][tx * 4 + j];
#pragma unroll
            for (int i = 0; i < 8; ++i)
#pragma unroll
                for (int j = 0; j < 4; ++j) acc[i][j] += a[i] * b[j];
        }

        if (it + 1 < nk) {
            const int nbuf = buf ^ 1;
            As[nbuf][ac4 + 0][ar0] = av0.x; As[nbuf][ac4 + 1][ar0] = av0.y;
            As[nbuf][ac4 + 2][ar0] = av0.z; As[nbuf][ac4 + 3][ar0] = av0.w;
            As[nbuf][ac4 + 0][ar1] = av1.x; As[nbuf][ac4 + 1][ar1] = av1.y;
            As[nbuf][ac4 + 2][ar1] = av1.z; As[nbuf][ac4 + 3][ar1] = av1.w;
            Ws[nbuf][ac4 + 0][wr]  = wv0.x; Ws[nbuf][ac4 + 1][wr]  = wv0.y;
            Ws[nbuf][ac4 + 2][wr]  = wv0.z; Ws[nbuf][ac4 + 3][wr]  = wv0.w;
            __syncthreads();
        }
    }

    // ---- epilogue: bias (+relu) + per-capsule L2 normalize ----
    const int gc0 = bn + tx * 4;
    float bvals[4];
#pragma unroll
    for (int j = 0; j < 4; ++j) bvals[j] = (gc0 + j < Ndim) ? bias[gc0 + j] : 0.f;

#pragma unroll
    for (int i = 0; i < 8; ++i) {
        int gr = bm + ty * 8 + i;
        float v[4];
        float ssq = 0.f;
#pragma unroll
        for (int j = 0; j < 4; ++j) {
            float val = (gc0 + j < Ndim) ? acc[i][j] + bvals[j] : 0.f;
            if (WRITE_RAW) val = fmaxf(val, 0.f);
            v[j] = val;
            ssq += val * val;
        }
        ssq += __shfl_xor_sync(0xffffffffu, ssq, 1);
        ssq += __shfl_xor_sync(0xffffffffu, ssq, 2);
        float inv = 1.f / fmaxf(sqrtf(ssq), 1e-12f);
        if (gr < Mdim && gc0 < Ndim) {
            if (WRITE_RAW) {
                float4 o = make_float4(v[0], v[1], v[2], v[3]);
                *reinterpret_cast<float4*>(rawOut + (size_t)gr * ldo + gc0) = o;
            }
            float4 no = make_float4(v[0] * inv, v[1] * inv, v[2] * inv, v[3] * inv);
            *reinterpret_cast<float4*>(xnorm + (size_t)gr * Ndim + gc0) = no;
            __half2 h0 = __floats2half2_rn(no.x, no.y);
            __half2 h1 = __floats2half2_rn(no.z, no.w);
            uint2 hp;
            hp.x = *reinterpret_cast<uint32_t*>(&h0);
            hp.y = *reinterpret_cast<uint32_t*>(&h1);
            *reinterpret_cast<uint2*>(xnormh + (size_t)gr * Ndim + gc0) = hp;
        }
    }
}

// ---------------------------------------------------------------------------
// Routing: one CTA per node, NT = 16*P threads. No smem z tile; fp16 u smem.
//  Phase A: z slice via 2 LDG.128 kept as packed fp16; u row = 2 LDS.128
//           (fp16, converted to fp32 for the dot).
//  Phase B: 8 LDG.64 fp16 z slices; ps (fp32, k-major) via 2 LDS.128;
//           xs4 (self term) from fp32 global, exact.
// ---------------------------------------------------------------------------
__device__ __forceinline__ float4 h4_to_f4(uint32_t lo, uint32_t hi)
{
    __half2 a = *reinterpret_cast<__half2*>(&lo);
    __half2 b = *reinterpret_cast<__half2*>(&hi);
    float2 fa = __half22float2(a);
    float2 fb = __half22float2(b);
    return make_float4(fa.x, fa.y, fb.x, fb.y);
}

template <int K>
__global__ void __launch_bounds__((K > 4) ? 128 : 64, (K > 4) ? 8 : 16)
routing_kernel(
    const float*  __restrict__ xnorm,
    const __half* __restrict__ xnormh,
    const int*    __restrict__ nbid,
    float* __restrict__ outp)   // already offset to this layer's column block
{
    constexpr int P  = (K > 4) ? 8 : 4;    // padded capsule count (pow2)
    constexpr int KD = K * 16;
    constexpr int Q  = K * 4;              // float4 per node row
    constexpr int UPH = 24;                // u row stride (halves): 48B rows
    constexpr int PST = 20;                // ps_t row stride (floats)

    const int n = blockIdx.x;
    const int tid = threadIdx.x;

    __shared__ __align__(16) __half uh[8 * UPH];  // fp16 u
    __shared__ __align__(16) float ps[8 * PST];   // k-major: ps[k*PST + m]
    __shared__ int nb[16];

    if (tid < 16) nb[tid] = __ldg(nbid + n * MNBR + tid);

    // init u = normalized self row -> fp16 padded layout
    if (tid < Q) {
        float4 v = reinterpret_cast<const float4*>(xnorm + (size_t)n * KD)[tid];
        __half2 h0 = __floats2half2_rn(v.x, v.y);
        __half2 h1 = __floats2half2_rn(v.z, v.w);
        uint2 hp;
        hp.x = *reinterpret_cast<uint32_t*>(&h0);
        hp.y = *reinterpret_cast<uint32_t*>(&h1);
        *reinterpret_cast<uint2*>(uh + (tid >> 2) * UPH + (tid & 3) * 4) = hp;
    }
    __syncthreads();

    // ---- phase-A mapping + packed fp16 z slice (direct LDG) ----
    const int mA = tid / P;
    const int kA = tid & (P - 1);
    const bool validA = (kA < K);
    const int kAc = validA ? kA : (K - 1);
    uint4 zr0, zr1;
    {
        const uint4* rowA = reinterpret_cast<const uint4*>(
            xnormh + (size_t)nb[mA] * KD + kAc * 16);
        zr0 = __ldg(rowA);
        zr1 = __ldg(rowA + 1);
    }

    // ---- phase-B mapping + fp16 z slices: tid = qB*2 + gB (8 m's/thread) ----
    const int qB = tid >> 1;
    const int gB = tid & 1;
    const bool validB = (tid < 2 * Q);
    const int qc = validB ? qB : (Q - 1);
    const int kB = qc >> 2;                // capsule of this q
    uint2 zah[8];
#pragma unroll
    for (int j = 0; j < 8; ++j)
        zah[j] = __ldg(reinterpret_cast<const uint2*>(
            xnormh + (size_t)nb[8 * gB + j] * KD + qc * 4));
    // self slice (exact fp32 from global; L1-hot)
    float4 xs4 = __ldg(reinterpret_cast<const float4*>(xnorm + (size_t)n * KD) + qc);

#pragma unroll
    for (int t = 0; t < 5; ++t) {
        // ---- A: agreement p[m][k] = <z[m,k,:], u[k,:]> ----
        float p;
        {
            const uint4* uptr = reinterpret_cast<const uint4*>(uh + kAc * UPH);
            uint4 u0 = uptr[0];
            uint4 u1 = uptr[1];
            float4 ua, zv;
            float pv = 0.f;
            ua = h4_to_f4(u0.x, u0.y); zv = h4_to_f4(zr0.x, zr0.y);
            pv += zv.x * ua.x + zv.y * ua.y + zv.z * ua.z + zv.w * ua.w;
            ua = h4_to_f4(u0.z, u0.w); zv = h4_to_f4(zr0.z, zr0.w);
            pv += zv.x * ua.x + zv.y * ua.y + zv.z * ua.z + zv.w * ua.w;
            ua = h4_to_f4(u1.x, u1.y); zv = h4_to_f4(zr1.x, zr1.y);
            pv += zv.x * ua.x + zv.y * ua.y + zv.z * ua.z + zv.w * ua.w;
            ua = h4_to_f4(u1.z, u1.w); zv = h4_to_f4(zr1.z, zr1.w);
            pv += zv.x * ua.x + zv.y * ua.y + zv.z * ua.z + zv.w * ua.w;
            p = validA ? pv : -1e30f;
        }
        // softmax over capsules (no max-sub: |p|<=~1, padding exp -> 0)
        float e = __expf(p);
        float s = e;
        s += __shfl_xor_sync(0xffffffffu, s, 1);
        s += __shfl_xor_sync(0xffffffffu, s, 2);
        if (P == 8) s += __shfl_xor_sync(0xffffffffu, s, 4);
        float pr = __fdividef(e, s);
        if (validA) ps[kA * PST + mA] = pr;     // k-major scatter (conflict-free)
        __syncthreads();

        // ---- B: u[k][:] = xself + sum_m z[m][k][:] * p[m][k] ----
        float4 pa = *reinterpret_cast<const float4*>(ps + kB * PST + 8 * gB);
        float4 pb = *reinterpret_cast<const float4*>(ps + kB * PST + 8 * gB + 4);
        float pm[8] = {pa.x, pa.y, pa.z, pa.w, pb.x, pb.y, pb.z, pb.w};
        float4 acc = make_float4(0.f, 0.f, 0.f, 0.f);
#pragma unroll
        for (int j = 0; j < 8; ++j) {
            float4 zm = h4_to_f4(zah[j].x, zah[j].y);
            acc.x += zm.x * pm[j]; acc.y += zm.y * pm[j];
            acc.z += zm.z * pm[j]; acc.w += zm.w * pm[j];
        }
        acc.x += __shfl_xor_sync(0xffffffffu, acc.x, 1);
        acc.y += __shfl_xor_sync(0xffffffffu, acc.y, 1);
        acc.z += __shfl_xor_sync(0xffffffffu, acc.z, 1);
        acc.w += __shfl_xor_sync(0xffffffffu, acc.w, 1);
        acc.x += xs4.x; acc.y += xs4.y; acc.z += xs4.z; acc.w += xs4.w;

        if (t < 4) {
            float sq = acc.x * acc.x + acc.y * acc.y + acc.z * acc.z + acc.w * acc.w;
            sq += __shfl_xor_sync(0xffffffffu, sq, 2);
            sq += __shfl_xor_sync(0xffffffffu, sq, 4);
            float inv = rsqrtf(fmaxf(sq, 1e-24f));
            if (validB && gB == 0) {
                __half2 h0 = __floats2half2_rn(acc.x * inv, acc.y * inv);
                __half2 h1 = __floats2half2_rn(acc.z * inv, acc.w * inv);
                uint2 hp;
                hp.x = *reinterpret_cast<uint32_t*>(&h0);
                hp.y = *reinterpret_cast<uint32_t*>(&h1);
                *reinterpret_cast<uint2*>(uh + kB * UPH + (qB & 3) * 4) = hp;
            }
            __syncthreads();
        } else if (validB && gB == 0) {
            float4 o = make_float4(fmaxf(acc.x, 0.f), fmaxf(acc.y, 0.f),
                                   fmaxf(acc.z, 0.f), fmaxf(acc.w, 0.f));
            *reinterpret_cast<float4*>(outp + (size_t)n * OUTW + qB * 4) = o;
        }
    }
}

// ---------------------------------------------------------------------------
// host orchestration
// ---------------------------------------------------------------------------
extern "C" void kernel_launch(void* const* d_in, const int* in_sizes, int n_in,
                              void* d_out, int out_size)
{
    (void)in_sizes; (void)n_in; (void)out_size;
    const float* feature = (const float*)d_in[0];
    const int*   nbid    = (const int*)d_in[1];
    const float* pca_w   = (const float*)d_in[2];
    const float* pca_b   = (const float*)d_in[3];
    const float* W[6]  = {nullptr, (const float*)d_in[4], (const float*)d_in[6],
                          (const float*)d_in[8], (const float*)d_in[10], (const float*)d_in[12]};
    const float* Bb[6] = {nullptr, (const float*)d_in[5], (const float*)d_in[7],
                          (const float*)d_in[9], (const float*)d_in[11], (const float*)d_in[13]};
    float* out = (float*)d_out;

    static const int caps[6]   = {8, 7, 6, 5, 4, 3};
    static const int coloff[7] = {0, 128, 256, 368, 464, 544, 608};

    float* xnorm;
    __half* xnormh;
    cudaGetSymbolAddress((void**)&xnorm,  g_xnorm);
    cudaGetSymbolAddress((void**)&xnormh, g_xnormh);

    const int mblocks = (NNODES + BM - 1) / BM;   // 157

    // PCA: x0 = relu(feature @ pca_w.T + pca_b) -> out[:,0:128] + xnorm(+h)
    {
        dim3 grid((128 + BN - 1) / BN, mblocks);
        gemm_norm_kernel<true><<<grid, 256>>>(feature, FEAT, pca_w, FEAT, pca_b,
                                              out, OUTW, xnorm, xnormh,
                                              NNODES, 128, FEAT);
    }

    for (int i = 0; i < 6; ++i) {
        int k = caps[i];
        int kd = k * 16;
        if (i > 0) {
            int fin = caps[i - 1] * 16;
            dim3 grid((kd + BN - 1) / BN, mblocks);
            gemm_norm_kernel<false><<<grid, 256>>>(out + coloff[i], OUTW,
                                                   W[i], fin, Bb[i],
                                                   nullptr, 0, xnorm, xnormh,
                                                   NNODES, kd, fin);
        }
        float* dst = out + coloff[i + 1];
        switch (k) {
            case 8: routing_kernel<8><<<NNODES, 128>>>(xnorm, xnormh, nbid, dst); break;
            case 7: routing_kernel<7><<<NNODES, 128>>>(xnorm, xnormh, nbid, dst); break;
            case 6: routing_kernel<6><<<NNODES, 128>>>(xnorm, xnormh, nbid, dst); break;
            case 5: routing_kernel<5><<<NNODES, 128>>>(xnorm, xnormh, nbid, dst); break;
            case 4: routing_kernel<4><<<NNODES, 64>>>(xnorm, xnormh, nbid, dst); break;
            case 3: routing_kernel<3><<<NNODES, 64>>>(xnorm, xnormh, nbid, dst); break;
        }
    }
}

// round 11
// speedup vs baseline: 1.4895x; 1.0213x over previous
#include <cuda_runtime.h>
#include <cuda_fp16.h>
#include <cstdint>

// ---------------------------------------------------------------------------
// DisenGCN on GB300: fused GEMM(+bias+relu+capsule-normalize) + capsule routing
// N=20000, M=16 neighbors, FEAT=500, d=16, CAPS={8,7,6,5,4,3}, 5 routing iters
// GEMM mainloop uses packed fma.rn.f32x2 (FFMA2) -- exact fp32, half the
// fma-pipe slots. Routing: z direct-LDG fp16 mirror, fp16 u smem, fp32 math.
// ---------------------------------------------------------------------------

#define NNODES 20000
#define MNBR   16
#define FEAT   500
#define OUTW   656

// scratch (device globals; no allocation allowed)
__device__ float  g_xnorm [NNODES * 128];  // fp32 normalized x
__device__ __half g_xnormh[NNODES * 128];  // fp16 mirror (neighbor gather)

// ---- packed f32x2 helpers (sm_103a FFMA2 via explicit PTX) ----------------
__device__ __forceinline__ unsigned long long f32x2_pack(float x, float y)
{
    unsigned long long r;
    asm("mov.b64 %0, {%1, %2};" : "=l"(r) : "f"(x), "f"(y));
    return r;
}
__device__ __forceinline__ void f32x2_unpack(unsigned long long v, float& x, float& y)
{
    asm("mov.b64 {%0, %1}, %2;" : "=f"(x), "=f"(y) : "l"(v));
}
__device__ __forceinline__ unsigned long long f32x2_fma(
    unsigned long long a, unsigned long long b, unsigned long long c)
{
    unsigned long long d;
    asm("fma.rn.f32x2 %0, %1, %2, %3;" : "=l"(d) : "l"(a), "l"(b), "l"(c));
    return d;
}

// ---------------------------------------------------------------------------
// GEMM: val[M,N] = (relu?)(A[M,K] @ W[N,K]^T + bias[N])
//   epilogue: per-16-col-capsule L2 normalize -> xnorm (fp32) + xnormh (fp16)
// BM=128, BN=64, BKK=16, 256 threads, 8x4 microtile (as 8x2 f32x2 pairs),
// double-buffered smem + register prefetch.
// ---------------------------------------------------------------------------
#define BM 128
#define BN 64
#define BKK 16

__device__ __forceinline__ float4 ldg4_guard(
    const float* __restrict__ P, int gr, int Rdim, int gc, int Kdim, int ld)
{
    float4 v = make_float4(0.f, 0.f, 0.f, 0.f);
    if (gr < Rdim) {
        if (gc + 3 < Kdim) {
            v = *reinterpret_cast<const float4*>(P + (size_t)gr * ld + gc);
        } else {
            const float* row = P + (size_t)gr * ld;
            if (gc + 0 < Kdim) v.x = row[gc + 0];
            if (gc + 1 < Kdim) v.y = row[gc + 1];
            if (gc + 2 < Kdim) v.z = row[gc + 2];
            if (gc + 3 < Kdim) v.w = row[gc + 3];
        }
    }
    return v;
}

template <bool WRITE_RAW>
__global__ void __launch_bounds__(256) gemm_norm_kernel(
    const float* __restrict__ A, int lda,
    const float* __restrict__ W, int ldw,
    const float* __restrict__ bias,
    float* __restrict__ rawOut, int ldo,
    float* __restrict__ xnorm,
    __half* __restrict__ xnormh,
    int Mdim, int Ndim, int Kdim)
{
    __shared__ float As[2][BKK][BM + 4];
    __shared__ float Ws[2][BKK][BN + 4];

    const int tid = threadIdx.x;
    const int tx = tid & 15;
    const int ty = tid >> 4;
    const int bm = blockIdx.y * BM;
    const int bn = blockIdx.x * BN;

    const int ar0 = tid >> 2;
    const int ac4 = (tid & 3) * 4;
    const int ar1 = (tid + 256) >> 2;
    const int wr  = tid >> 2;

    // packed accumulators: acc[i][0] = cols(j0,j1), acc[i][1] = cols(j2,j3)
    unsigned long long accp[8][2];
    const unsigned long long zz = f32x2_pack(0.f, 0.f);
#pragma unroll
    for (int i = 0; i < 8; ++i) { accp[i][0] = zz; accp[i][1] = zz; }

    const int nk = (Kdim + BKK - 1) / BKK;

    float4 av0, av1, wv0;
    av0 = ldg4_guard(A, bm + ar0, Mdim, 0 + ac4, Kdim, lda);
    av1 = ldg4_guard(A, bm + ar1, Mdim, 0 + ac4, Kdim, lda);
    wv0 = ldg4_guard(W, bn + wr,  Ndim, 0 + ac4, Kdim, ldw);
    {
        As[0][ac4 + 0][ar0] = av0.x; As[0][ac4 + 1][ar0] = av0.y;
        As[0][ac4 + 2][ar0] = av0.z; As[0][ac4 + 3][ar0] = av0.w;
        As[0][ac4 + 0][ar1] = av1.x; As[0][ac4 + 1][ar1] = av1.y;
        As[0][ac4 + 2][ar1] = av1.z; As[0][ac4 + 3][ar1] = av1.w;
        Ws[0][ac4 + 0][wr]  = wv0.x; Ws[0][ac4 + 1][wr]  = wv0.y;
        Ws[0][ac4 + 2][wr]  = wv0.z; Ws[0][ac4 + 3][wr]  = wv0.w;
    }
    __syncthreads();

    for (int it = 0; it < nk; ++it) {
        const int buf = it & 1;
        if (it + 1 < nk) {
            int k0 = (it + 1) * BKK;
            av0 = ldg4_guard(A, bm + ar0, Mdim, k0 + ac4, Kdim, lda);
            av1 = ldg4_guard(A, bm + ar1, Mdim, k0 + ac4, Kdim, lda);
            wv0 = ldg4_guard(W, bn + wr,  Ndim, k0 + ac4, Kdim, ldw);
        }

#pragma unroll
        for (int kk = 0; kk < BKK; ++kk) {
            // b pairs: 2x LDS.64 (8B-aligned: row stride 272B, offset 16B*tx)
            unsigned long long b01 =
                *reinterpret_cast<const unsigned long long*>(&Ws[buf][kk][tx * 4]);
            unsigned long long b23 =
                *reinterpret_cast<const unsigned long long*>(&Ws[buf][kk][tx * 4 + 2]);
            float a_s[8];
#pragma unroll
            for (int i = 0; i < 8; ++i) a_s[i] = As[buf][kk][ty * 8 + i];
#pragma unroll
            for (int i = 0; i < 8; ++i) {
                unsigned long long aa = f32x2_pack(a_s[i], a_s[i]);
                accp[i][0] = f32x2_fma(aa, b01, accp[i][0]);
                accp[i][1] = f32x2_fma(aa, b23, accp[i][1]);
            }
        }

        if (it + 1 < nk) {
            const int nbuf = buf ^ 1;
            As[nbuf][ac4 + 0][ar0] = av0.x; As[nbuf][ac4 + 1][ar0] = av0.y;
            As[nbuf][ac4 + 2][ar0] = av0.z; As[nbuf][ac4 + 3][ar0] = av0.w;
            As[nbuf][ac4 + 0][ar1] = av1.x; As[nbuf][ac4 + 1][ar1] = av1.y;
            As[nbuf][ac4 + 2][ar1] = av1.z; As[nbuf][ac4 + 3][ar1] = av1.w;
            Ws[nbuf][ac4 + 0][wr]  = wv0.x; Ws[nbuf][ac4 + 1][wr]  = wv0.y;
            Ws[nbuf][ac4 + 2][wr]  = wv0.z; Ws[nbuf][ac4 + 3][wr]  = wv0.w;
            __syncthreads();
        }
    }

    // ---- epilogue: bias (+relu) + per-capsule L2 normalize ----
    const int gc0 = bn + tx * 4;
    float bvals[4];
#pragma unroll
    for (int j = 0; j < 4; ++j) bvals[j] = (gc0 + j < Ndim) ? bias[gc0 + j] : 0.f;

#pragma unroll
    for (int i = 0; i < 8; ++i) {
        int gr = bm + ty * 8 + i;
        float a0, a1, a2, a3;
        f32x2_unpack(accp[i][0], a0, a1);
        f32x2_unpack(accp[i][1], a2, a3);
        float accv[4] = {a0, a1, a2, a3};
        float v[4];
        float ssq = 0.f;
#pragma unroll
        for (int j = 0; j < 4; ++j) {
            float val = (gc0 + j < Ndim) ? accv[j] + bvals[j] : 0.f;
            if (WRITE_RAW) val = fmaxf(val, 0.f);
            v[j] = val;
            ssq += val * val;
        }
        ssq += __shfl_xor_sync(0xffffffffu, ssq, 1);
        ssq += __shfl_xor_sync(0xffffffffu, ssq, 2);
        float inv = 1.f / fmaxf(sqrtf(ssq), 1e-12f);
        if (gr < Mdim && gc0 < Ndim) {
            if (WRITE_RAW) {
                float4 o = make_float4(v[0], v[1], v[2], v[3]);
                *reinterpret_cast<float4*>(rawOut + (size_t)gr * ldo + gc0) = o;
            }
            float4 no = make_float4(v[0] * inv, v[1] * inv, v[2] * inv, v[3] * inv);
            *reinterpret_cast<float4*>(xnorm + (size_t)gr * Ndim + gc0) = no;
            __half2 h0 = __floats2half2_rn(no.x, no.y);
            __half2 h1 = __floats2half2_rn(no.z, no.w);
            uint2 hp;
            hp.x = *reinterpret_cast<uint32_t*>(&h0);
            hp.y = *reinterpret_cast<uint32_t*>(&h1);
            *reinterpret_cast<uint2*>(xnormh + (size_t)gr * Ndim + gc0) = hp;
        }
    }
}

// ---------------------------------------------------------------------------
// Routing (R10 winner, unchanged): one CTA per node, NT = 16*P threads.
//  Phase A: z slice via 2 LDG.128 packed fp16; u row = 2 LDS.128 fp16.
//  Phase B: 8 LDG.64 fp16 z slices; ps (fp32, k-major); xs4 exact fp32.
// ---------------------------------------------------------------------------
__device__ __forceinline__ float4 h4_to_f4(uint32_t lo, uint32_t hi)
{
    __half2 a = *reinterpret_cast<__half2*>(&lo);
    __half2 b = *reinterpret_cast<__half2*>(&hi);
    float2 fa = __half22float2(a);
    float2 fb = __half22float2(b);
    return make_float4(fa.x, fa.y, fb.x, fb.y);
}

template <int K>
__global__ void __launch_bounds__((K > 4) ? 128 : 64, (K > 4) ? 8 : 16)
routing_kernel(
    const float*  __restrict__ xnorm,
    const __half* __restrict__ xnormh,
    const int*    __restrict__ nbid,
    float* __restrict__ outp)
{
    constexpr int P  = (K > 4) ? 8 : 4;
    constexpr int KD = K * 16;
    constexpr int Q  = K * 4;
    constexpr int UPH = 24;                // u row stride (halves): 48B rows
    constexpr int PST = 20;                // ps_t row stride (floats)

    const int n = blockIdx.x;
    const int tid = threadIdx.x;

    __shared__ __align__(16) __half uh[8 * UPH];
    __shared__ __align__(16) float ps[8 * PST];
    __shared__ int nb[16];

    if (tid < 16) nb[tid] = __ldg(nbid + n * MNBR + tid);

    if (tid < Q) {
        float4 v = reinterpret_cast<const float4*>(xnorm + (size_t)n * KD)[tid];
        __half2 h0 = __floats2half2_rn(v.x, v.y);
        __half2 h1 = __floats2half2_rn(v.z, v.w);
        uint2 hp;
        hp.x = *reinterpret_cast<uint32_t*>(&h0);
        hp.y = *reinterpret_cast<uint32_t*>(&h1);
        *reinterpret_cast<uint2*>(uh + (tid >> 2) * UPH + (tid & 3) * 4) = hp;
    }
    __syncthreads();

    const int mA = tid / P;
    const int kA = tid & (P - 1);
    const bool validA = (kA < K);
    const int kAc = validA ? kA : (K - 1);
    uint4 zr0, zr1;
    {
        const uint4* rowA = reinterpret_cast<const uint4*>(
            xnormh + (size_t)nb[mA] * KD + kAc * 16);
        zr0 = __ldg(rowA);
        zr1 = __ldg(rowA + 1);
    }

    const int qB = tid >> 1;
    const int gB = tid & 1;
    const bool validB = (tid < 2 * Q);
    const int qc = validB ? qB : (Q - 1);
    const int kB = qc >> 2;
    uint2 zah[8];
#pragma unroll
    for (int j = 0; j < 8; ++j)
        zah[j] = __ldg(reinterpret_cast<const uint2*>(
            xnormh + (size_t)nb[8 * gB + j] * KD + qc * 4));
    float4 xs4 = __ldg(reinterpret_cast<const float4*>(xnorm + (size_t)n * KD) + qc);

#pragma unroll
    for (int t = 0; t < 5; ++t) {
        float p;
        {
            const uint4* uptr = reinterpret_cast<const uint4*>(uh + kAc * UPH);
            uint4 u0 = uptr[0];
            uint4 u1 = uptr[1];
            float4 ua, zv;
            float pv = 0.f;
            ua = h4_to_f4(u0.x, u0.y); zv = h4_to_f4(zr0.x, zr0.y);
            pv += zv.x * ua.x + zv.y * ua.y + zv.z * ua.z + zv.w * ua.w;
            ua = h4_to_f4(u0.z, u0.w); zv = h4_to_f4(zr0.z, zr0.w);
            pv += zv.x * ua.x + zv.y * ua.y + zv.z * ua.z + zv.w * ua.w;
            ua = h4_to_f4(u1.x, u1.y); zv = h4_to_f4(zr1.x, zr1.y);
            pv += zv.x * ua.x + zv.y * ua.y + zv.z * ua.z + zv.w * ua.w;
            ua = h4_to_f4(u1.z, u1.w); zv = h4_to_f4(zr1.z, zr1.w);
            pv += zv.x * ua.x + zv.y * ua.y + zv.z * ua.z + zv.w * ua.w;
            p = validA ? pv : -1e30f;
        }
        float e = __expf(p);
        float s = e;
        s += __shfl_xor_sync(0xffffffffu, s, 1);
        s += __shfl_xor_sync(0xffffffffu, s, 2);
        if (P == 8) s += __shfl_xor_sync(0xffffffffu, s, 4);
        float pr = __fdividef(e, s);
        if (validA) ps[kA * PST + mA] = pr;
        __syncthreads();

        float4 pa = *reinterpret_cast<const float4*>(ps + kB * PST + 8 * gB);
        float4 pb = *reinterpret_cast<const float4*>(ps + kB * PST + 8 * gB + 4);
        float pm[8] = {pa.x, pa.y, pa.z, pa.w, pb.x, pb.y, pb.z, pb.w};
        float4 acc = make_float4(0.f, 0.f, 0.f, 0.f);
#pragma unroll
        for (int j = 0; j < 8; ++j) {
            float4 zm = h4_to_f4(zah[j].x, zah[j].y);
            acc.x += zm.x * pm[j]; acc.y += zm.y * pm[j];
            acc.z += zm.z * pm[j]; acc.w += zm.w * pm[j];
        }
        acc.x += __shfl_xor_sync(0xffffffffu, acc.x, 1);
        acc.y += __shfl_xor_sync(0xffffffffu, acc.y, 1);
        acc.z += __shfl_xor_sync(0xffffffffu, acc.z, 1);
        acc.w += __shfl_xor_sync(0xffffffffu, acc.w, 1);
        acc.x += xs4.x; acc.y += xs4.y; acc.z += xs4.z; acc.w += xs4.w;

        if (t < 4) {
            float sq = acc.x * acc.x + acc.y * acc.y + acc.z * acc.z + acc.w * acc.w;
            sq += __shfl_xor_sync(0xffffffffu, sq, 2);
            sq += __shfl_xor_sync(0xffffffffu, sq, 4);
            float inv = rsqrtf(fmaxf(sq, 1e-24f));
            if (validB && gB == 0) {
                __half2 h0 = __floats2half2_rn(acc.x * inv, acc.y * inv);
                __half2 h1 = __floats2half2_rn(acc.z * inv, acc.w * inv);
                uint2 hp;
                hp.x = *reinterpret_cast<uint32_t*>(&h0);
                hp.y = *reinterpret_cast<uint32_t*>(&h1);
                *reinterpret_cast<uint2*>(uh + kB * UPH + (qB & 3) * 4) = hp;
            }
            __syncthreads();
        } else if (validB && gB == 0) {
            float4 o = make_float4(fmaxf(acc.x, 0.f), fmaxf(acc.y, 0.f),
                                   fmaxf(acc.z, 0.f), fmaxf(acc.w, 0.f));
            *reinterpret_cast<float4*>(outp + (size_t)n * OUTW + qB * 4) = o;
        }
    }
}

// ---------------------------------------------------------------------------
// host orchestration
// ---------------------------------------------------------------------------
extern "C" void kernel_launch(void* const* d_in, const int* in_sizes, int n_in,
                              void* d_out, int out_size)
{
    (void)in_sizes; (void)n_in; (void)out_size;
    const float* feature = (const float*)d_in[0];
    const int*   nbid    = (const int*)d_in[1];
    const float* pca_w   = (const float*)d_in[2];
    const float* pca_b   = (const float*)d_in[3];
    const float* W[6]  = {nullptr, (const float*)d_in[4], (const float*)d_in[6],
                          (const float*)d_in[8], (const float*)d_in[10], (const float*)d_in[12]};
    const float* Bb[6] = {nullptr, (const float*)d_in[5], (const float*)d_in[7],
                          (const float*)d_in[9], (const float*)d_in[11], (const float*)d_in[13]};
    float* out = (float*)d_out;

    static const int caps[6]   = {8, 7, 6, 5, 4, 3};
    static const int coloff[7] = {0, 128, 256, 368, 464, 544, 608};

    float* xnorm;
    __half* xnormh;
    cudaGetSymbolAddress((void**)&xnorm,  g_xnorm);
    cudaGetSymbolAddress((void**)&xnormh, g_xnormh);

    const int mblocks = (NNODES + BM - 1) / BM;   // 157

    // PCA: x0 = relu(feature @ pca_w.T + pca_b) -> out[:,0:128] + xnorm(+h)
    {
        dim3 grid((128 + BN - 1) / BN, mblocks);
        gemm_norm_kernel<true><<<grid, 256>>>(feature, FEAT, pca_w, FEAT, pca_b,
                                              out, OUTW, xnorm, xnormh,
                                              NNODES, 128, FEAT);
    }

    for (int i = 0; i < 6; ++i) {
        int k = caps[i];
        int kd = k * 16;
        if (i > 0) {
            int fin = caps[i - 1] * 16;
            dim3 grid((kd + BN - 1) / BN, mblocks);
            gemm_norm_kernel<false><<<grid, 256>>>(out + coloff[i], OUTW,
                                                   W[i], fin, Bb[i],
                                                   nullptr, 0, xnorm, xnormh,
                                                   NNODES, kd, fin);
        }
        float* dst = out + coloff[i + 1];
        switch (k) {
            case 8: routing_kernel<8><<<NNODES, 128>>>(xnorm, xnormh, nbid, dst); break;
            case 7: routing_kernel<7><<<NNODES, 128>>>(xnorm, xnormh, nbid, dst); break;
            case 6: routing_kernel<6><<<NNODES, 128>>>(xnorm, xnormh, nbid, dst); break;
            case 5: routing_kernel<5><<<NNODES, 128>>>(xnorm, xnormh, nbid, dst); break;
            case 4: routing_kernel<4><<<NNODES, 64>>>(xnorm, xnormh, nbid, dst); break;
            case 3: routing_kernel<3><<<NNODES, 64>>>(xnorm, xnormh, nbid, dst); break;
        }
    }
}